// round 1
// baseline (speedup 1.0000x reference)
#include <cuda_runtime.h>
#include <cuda_bf16.h>
#include <math.h>

// Problem constants
#define SEQ_TXT 256
#define SEQ_IMG 2048
#define SEQ_TOT 2304          // 256 + 2048
#define DMODEL  3072
#define NHEADS  24
#define DHEAD   128
#define SS      (2304LL*2304LL)   // per-head score matrix elements

// Scratch (static __device__ globals — no allocation APIs allowed)
__device__ float g_q[SEQ_TOT * DMODEL];
__device__ float g_k[SEQ_TOT * DMODEL];
__device__ float g_v[SEQ_TOT * DMODEL];
__device__ float g_attn[SEQ_TOT * DMODEL];
__device__ float g_s[24LL * 2304LL * 2304LL];   // ~510 MB

// ---------------------------------------------------------------------------
// Generic batched SGEMM: C = alpha * A@B (+bias), 128x128x8 tiles, 8x8 micro.
// NT=true: B accessed as B[n*ldb + k] (dot-of-rows, for Q@K^T).
// All dims assumed divisible by tile sizes (holds for every call here).
// ---------------------------------------------------------------------------
template<bool NT, bool BIAS>
__global__ __launch_bounds__(256) void gemm_kernel(
    const float* __restrict__ A, int lda, long strideA,
    const float* __restrict__ B, int ldb, long strideB,
    float*       __restrict__ C, int ldc, long strideC,
    int M, int N, int K,
    const float* __restrict__ bias, float alpha)
{
    const int bz = blockIdx.z;
    A += (long)bz * strideA;
    B += (long)bz * strideB;
    C += (long)bz * strideC;

    const int row0 = blockIdx.y * 128;
    const int col0 = blockIdx.x * 128;

    __shared__ float As[8][128];
    __shared__ float Bs[8][128];

    const int tid = threadIdx.x;
    // A-tile (and NT B-tile) loader mapping: 128 rows x 8 k, float4 along k
    const int aRow = tid >> 1;
    const int aK4  = (tid & 1) * 4;
    // NN B-tile loader mapping: 8 k-rows x 128 cols, float4 along n
    const int bRowNN = tid >> 5;
    const int bCol4  = (tid & 31) * 4;

    const int tx = tid & 15;   // 16 col-threads * 8 = 128
    const int ty = tid >> 4;   // 16 row-threads * 8 = 128

    float acc[8][8];
    #pragma unroll
    for (int i = 0; i < 8; i++)
        #pragma unroll
        for (int j = 0; j < 8; j++) acc[i][j] = 0.0f;

    const float* Aptr = A + (long)(row0 + aRow) * lda + aK4;
    const float* Bptr;
    if (NT) Bptr = B + (long)(col0 + aRow) * ldb + aK4;
    else    Bptr = B + (long)bRowNN * ldb + col0 + bCol4;

    for (int k0 = 0; k0 < K; k0 += 8) {
        float4 av = *(const float4*)(Aptr + k0);
        As[aK4 + 0][aRow] = av.x;
        As[aK4 + 1][aRow] = av.y;
        As[aK4 + 2][aRow] = av.z;
        As[aK4 + 3][aRow] = av.w;
        if (NT) {
            float4 bv = *(const float4*)(Bptr + k0);
            Bs[aK4 + 0][aRow] = bv.x;
            Bs[aK4 + 1][aRow] = bv.y;
            Bs[aK4 + 2][aRow] = bv.z;
            Bs[aK4 + 3][aRow] = bv.w;
        } else {
            float4 bv = *(const float4*)(Bptr + (long)k0 * ldb);
            *(float4*)&Bs[bRowNN][bCol4] = bv;
        }
        __syncthreads();

        #pragma unroll
        for (int k = 0; k < 8; ++k) {
            float a[8], b[8];
            *(float4*)(a + 0) = *(const float4*)&As[k][ty * 8 + 0];
            *(float4*)(a + 4) = *(const float4*)&As[k][ty * 8 + 4];
            *(float4*)(b + 0) = *(const float4*)&Bs[k][tx * 8 + 0];
            *(float4*)(b + 4) = *(const float4*)&Bs[k][tx * 8 + 4];
            #pragma unroll
            for (int i = 0; i < 8; i++)
                #pragma unroll
                for (int j = 0; j < 8; j++)
                    acc[i][j] += a[i] * b[j];
        }
        __syncthreads();
    }

    // Epilogue
    #pragma unroll
    for (int i = 0; i < 8; i++) {
        long row = row0 + ty * 8 + i;
        float* cp = C + row * (long)ldc + col0 + tx * 8;
        #pragma unroll
        for (int j = 0; j < 8; j += 4) {
            float4 o;
            o.x = acc[i][j + 0] * alpha;
            o.y = acc[i][j + 1] * alpha;
            o.z = acc[i][j + 2] * alpha;
            o.w = acc[i][j + 3] * alpha;
            if (BIAS) {
                const float* bp = bias + col0 + tx * 8 + j;
                o.x += bp[0]; o.y += bp[1]; o.z += bp[2]; o.w += bp[3];
            }
            *(float4*)(cp + j) = o;
        }
    }
}

// ---------------------------------------------------------------------------
// Fused per-head RMSNorm + RoPE. One warp per (s, h) row of 128 elements.
// txt rows (s < 256) use g_txt gains, img rows use g_img gains.
// ---------------------------------------------------------------------------
__global__ __launch_bounds__(128) void norm_rope_kernel(
    float* __restrict__ x,
    const float* __restrict__ g_img,
    const float* __restrict__ g_txt,
    const float* __restrict__ freqs)
{
    int r = blockIdx.x * 4 + (threadIdx.x >> 5);   // r = s*24 + h
    int lane = threadIdx.x & 31;
    int s = r / NHEADS;

    float* p = x + (long)r * DHEAD + lane * 4;
    float4 v = *(const float4*)p;

    float ss = v.x * v.x + v.y * v.y + v.z * v.z + v.w * v.w;
    #pragma unroll
    for (int o = 16; o; o >>= 1) ss += __shfl_xor_sync(0xffffffffu, ss, o);
    float rn = rsqrtf(ss * (1.0f / 128.0f) + 1e-5f);

    const float* g = (s < SEQ_TXT) ? g_txt : g_img;
    int d = lane * 4;
    float x0 = v.x * rn * g[d + 0];
    float x1 = v.y * rn * g[d + 1];
    float x2 = v.z * rn * g[d + 2];
    float x3 = v.w * rn * g[d + 3];

    // freqs layout: [s][0][d2][j][i] -> s*256 + d2*4 + j*2 + i ; d2 = d/2
    const float* f = freqs + (long)s * 256 + (d / 2) * 4;
    float4 o;
    o.x = f[0] * x0 + f[1] * x1;
    o.y = f[2] * x0 + f[3] * x1;
    o.z = f[4] * x2 + f[5] * x3;
    o.w = f[6] * x2 + f[7] * x3;
    *(float4*)p = o;
}

// ---------------------------------------------------------------------------
// Row softmax over 2304 elements. One block (256 thr) per row; exact max/sum.
// ---------------------------------------------------------------------------
__global__ __launch_bounds__(256) void softmax_kernel(float* __restrict__ S)
{
    long row = blockIdx.x;
    float* p = S + row * 2304;
    int tid = threadIdx.x;

    float v[9];
    float mx = -INFINITY;
    #pragma unroll
    for (int i = 0; i < 9; i++) {
        v[i] = p[tid + i * 256];
        mx = fmaxf(mx, v[i]);
    }

    __shared__ float red[8];
    #pragma unroll
    for (int o = 16; o; o >>= 1) mx = fmaxf(mx, __shfl_xor_sync(0xffffffffu, mx, o));
    if ((tid & 31) == 0) red[tid >> 5] = mx;
    __syncthreads();
    float m = red[0];
    #pragma unroll
    for (int i = 1; i < 8; i++) m = fmaxf(m, red[i]);
    __syncthreads();

    float sum = 0.0f;
    #pragma unroll
    for (int i = 0; i < 9; i++) {
        v[i] = __expf(v[i] - m);
        sum += v[i];
    }
    #pragma unroll
    for (int o = 16; o; o >>= 1) sum += __shfl_xor_sync(0xffffffffu, sum, o);
    if ((tid & 31) == 0) red[tid >> 5] = sum;
    __syncthreads();
    float tot = 0.0f;
    #pragma unroll
    for (int i = 0; i < 8; i++) tot += red[i];
    float inv = 1.0f / tot;

    #pragma unroll
    for (int i = 0; i < 9; i++) p[tid + i * 256] = v[i] * inv;
}

// ---------------------------------------------------------------------------
// Launch
// ---------------------------------------------------------------------------
extern "C" void kernel_launch(void* const* d_in, const int* in_sizes, int n_in,
                              void* d_out, int out_size)
{
    const float* hid   = (const float*)d_in[0];   // [1,2048,3072]
    const float* enc   = (const float*)d_in[1];   // [1,256,3072]
    const float* freqs = (const float*)d_in[2];   // [2304,1,64,2,2]
    const float* Wq  = (const float*)d_in[3];
    const float* Wk  = (const float*)d_in[4];
    const float* Wv  = (const float*)d_in[5];
    const float* Waq = (const float*)d_in[6];
    const float* Wak = (const float*)d_in[7];
    const float* Wav = (const float*)d_in[8];
    const float* gq  = (const float*)d_in[9];
    const float* gk  = (const float*)d_in[10];
    const float* gaq = (const float*)d_in[11];
    const float* gak = (const float*)d_in[12];
    const float* Wo  = (const float*)d_in[13];
    const float* bo  = (const float*)d_in[14];
    const float* Wao = (const float*)d_in[15];
    const float* bao = (const float*)d_in[16];
    float* out = (float*)d_out;

    float *q, *k, *v, *attn, *sc;
    cudaGetSymbolAddress((void**)&q,    g_q);
    cudaGetSymbolAddress((void**)&k,    g_k);
    cudaGetSymbolAddress((void**)&v,    g_v);
    cudaGetSymbolAddress((void**)&attn, g_attn);
    cudaGetSymbolAddress((void**)&sc,   g_s);

    dim3 blk(256);

    // --- QKV projections (txt rows 0..255, img rows 256..2303) ---
    // txt: M=256 -> grid(24,2) ; img: M=2048 -> grid(24,16)
    gemm_kernel<false,false><<<dim3(24, 2, 1), blk>>>(
        enc, DMODEL, 0, Waq, DMODEL, 0, q, DMODEL, 0, SEQ_TXT, DMODEL, DMODEL, nullptr, 1.0f);
    gemm_kernel<false,false><<<dim3(24, 16, 1), blk>>>(
        hid, DMODEL, 0, Wq, DMODEL, 0, q + (long)SEQ_TXT * DMODEL, DMODEL, 0, SEQ_IMG, DMODEL, DMODEL, nullptr, 1.0f);

    gemm_kernel<false,false><<<dim3(24, 2, 1), blk>>>(
        enc, DMODEL, 0, Wak, DMODEL, 0, k, DMODEL, 0, SEQ_TXT, DMODEL, DMODEL, nullptr, 1.0f);
    gemm_kernel<false,false><<<dim3(24, 16, 1), blk>>>(
        hid, DMODEL, 0, Wk, DMODEL, 0, k + (long)SEQ_TXT * DMODEL, DMODEL, 0, SEQ_IMG, DMODEL, DMODEL, nullptr, 1.0f);

    gemm_kernel<false,false><<<dim3(24, 2, 1), blk>>>(
        enc, DMODEL, 0, Wav, DMODEL, 0, v, DMODEL, 0, SEQ_TXT, DMODEL, DMODEL, nullptr, 1.0f);
    gemm_kernel<false,false><<<dim3(24, 16, 1), blk>>>(
        hid, DMODEL, 0, Wv, DMODEL, 0, v + (long)SEQ_TXT * DMODEL, DMODEL, 0, SEQ_IMG, DMODEL, DMODEL, nullptr, 1.0f);

    // --- RMSNorm + RoPE on q and k (55296 rows, 4 rows/block of 128 thr) ---
    norm_rope_kernel<<<SEQ_TOT * NHEADS / 4, 128>>>(q, gq, gaq, freqs);
    norm_rope_kernel<<<SEQ_TOT * NHEADS / 4, 128>>>(k, gk, gak, freqs);

    // --- Scores: S_h = scale * Q_h @ K_h^T  (per head, NT) ---
    const float scale = 0.088388347648318447f;  // 1/sqrt(128)
    gemm_kernel<true,false><<<dim3(18, 18, 24), blk>>>(
        q, DMODEL, 128, k, DMODEL, 128, sc, 2304, SS, SEQ_TOT, SEQ_TOT, DHEAD, nullptr, scale);

    // --- Softmax over each of 24*2304 rows ---
    softmax_kernel<<<NHEADS * SEQ_TOT, 256>>>(sc);

    // --- PV: attn_h = P_h @ V_h (per head, NN) ---
    gemm_kernel<false,false><<<dim3(1, 18, 24), blk>>>(
        sc, 2304, SS, v, DMODEL, 128, attn, DMODEL, 128, SEQ_TOT, DHEAD, SEQ_TOT, nullptr, 1.0f);

    // --- Output projections: img_out first (reference returns (img, txt)) ---
    gemm_kernel<false,true><<<dim3(24, 16, 1), blk>>>(
        attn + (long)SEQ_TXT * DMODEL, DMODEL, 0, Wo, DMODEL, 0,
        out, DMODEL, 0, SEQ_IMG, DMODEL, DMODEL, bo, 1.0f);
    gemm_kernel<false,true><<<dim3(24, 2, 1), blk>>>(
        attn, DMODEL, 0, Wao, DMODEL, 0,
        out + (long)SEQ_IMG * DMODEL, DMODEL, 0, SEQ_TXT, DMODEL, DMODEL, bao, 1.0f);
}

// round 3
// speedup vs baseline: 1.8816x; 1.8816x over previous
#include <cuda_runtime.h>
#include <cuda_bf16.h>
#include <math.h>
#include <stdint.h>

// Problem constants
#define SEQ_TXT 256
#define SEQ_IMG 2048
#define SEQ_TOT 2304
#define DMODEL  3072
#define NHEADS  24
#define DHEAD   128
#define SS      (2304LL*2304LL)

// Scratch
__device__ float g_q[SEQ_TOT * DMODEL];
__device__ float g_k[SEQ_TOT * DMODEL];
__device__ float g_v[SEQ_TOT * DMODEL];
__device__ float g_attn[SEQ_TOT * DMODEL];
__device__ float g_vt[DMODEL * SEQ_TOT];                 // V transposed (per-head rows)
__device__ float g_wt[8][DMODEL * (long)DMODEL];         // transposed weights
__device__ float g_s[24LL * 2304LL * 2304LL];            // ~510 MB scores

__device__ __forceinline__ float tf32r(float x) {
    uint32_t u;
    asm("cvt.rna.tf32.f32 %0, %1;" : "=r"(u) : "f"(x));
    return __uint_as_float(u);
}

// ---------------------------------------------------------------------------
// 32x32 tiled transpose: out[c][r] = in[r][c]
// ---------------------------------------------------------------------------
__global__ __launch_bounds__(256) void transpose_kernel(
    const float* __restrict__ in, float* __restrict__ out, int rows, int cols)
{
    __shared__ float t[32][33];
    int bx = blockIdx.x * 32;
    int by = blockIdx.y * 32;
    int x = bx + threadIdx.x;
    #pragma unroll
    for (int j = 0; j < 32; j += 8)
        t[threadIdx.y + j][threadIdx.x] = in[(long)(by + threadIdx.y + j) * cols + x];
    __syncthreads();
    int y = by + threadIdx.x;
    #pragma unroll
    for (int j = 0; j < 32; j += 8)
        out[(long)(bx + threadIdx.y + j) * rows + y] = t[threadIdx.x][threadIdx.y + j];
}

// ---------------------------------------------------------------------------
// 3xTF32 tensor-core GEMM: C = alpha * A @ B^T (+bias), near-fp32 accuracy.
// A: M x K row-major. B: N x K row-major ("NT").
// Tiles 128x128x32, 8 warps (32x64 each), double-buffered hi/lo smem.
// ---------------------------------------------------------------------------
#define SMEM_STRIDE 36
#define ABUF (128 * SMEM_STRIDE)
// layout: [AHI x2][ALO x2][BHI x2][BLO x2], each ABUF floats
#define SMEMB_TOTAL (8 * ABUF * 4)

template<bool BIAS>
__global__ __launch_bounds__(256) void tgemm(
    const float* __restrict__ A, int lda, long sA,
    const float* __restrict__ B, int ldb, long sB,
    float*       __restrict__ C, int ldc, long sC,
    int K, const float* __restrict__ bias, float alpha)
{
    extern __shared__ float sm[];
    float* smAhi = sm;
    float* smAlo = sm + 2 * ABUF;
    float* smBhi = sm + 4 * ABUF;
    float* smBlo = sm + 6 * ABUF;

    const int bz = blockIdx.z;
    A += (long)bz * sA;
    B += (long)bz * sB;
    C += (long)bz * sC;

    const int row0 = blockIdx.y * 128;
    const int col0 = blockIdx.x * 128;

    const int tid  = threadIdx.x;
    const int lane = tid & 31;
    const int wid  = tid >> 5;
    const int m_off = (wid & 3) * 32;
    const int n_off = (wid >> 2) * 64;
    const int lr = lane >> 2;
    const int lc = lane & 3;

    const int gr  = tid >> 3;         // 0..31
    const int gc4 = (tid & 7) * 4;    // 0..28
    const float* Ag = A + (long)(row0 + gr) * lda + gc4;
    const float* Bg = B + (long)(col0 + gr) * ldb + gc4;

    float4 ra[4], rb[4];

    auto stage = [&](int buf) {
        float* dAh = smAhi + buf * ABUF;
        float* dAl = smAlo + buf * ABUF;
        float* dBh = smBhi + buf * ABUF;
        float* dBl = smBlo + buf * ABUF;
        #pragma unroll
        for (int p = 0; p < 4; p++) {
            int off = (gr + p * 32) * SMEM_STRIDE + gc4;
            float a0 = ra[p].x, a1 = ra[p].y, a2 = ra[p].z, a3 = ra[p].w;
            float h0 = tf32r(a0), h1 = tf32r(a1), h2 = tf32r(a2), h3 = tf32r(a3);
            dAh[off + 0] = h0; dAh[off + 1] = h1; dAh[off + 2] = h2; dAh[off + 3] = h3;
            dAl[off + 0] = tf32r(a0 - h0); dAl[off + 1] = tf32r(a1 - h1);
            dAl[off + 2] = tf32r(a2 - h2); dAl[off + 3] = tf32r(a3 - h3);
            float b0 = rb[p].x, b1 = rb[p].y, b2 = rb[p].z, b3 = rb[p].w;
            float i0 = tf32r(b0), i1 = tf32r(b1), i2 = tf32r(b2), i3 = tf32r(b3);
            dBh[off + 0] = i0; dBh[off + 1] = i1; dBh[off + 2] = i2; dBh[off + 3] = i3;
            dBl[off + 0] = tf32r(b0 - i0); dBl[off + 1] = tf32r(b1 - i1);
            dBl[off + 2] = tf32r(b2 - i2); dBl[off + 3] = tf32r(b3 - i3);
        }
    };

    // preload k-tile 0
    #pragma unroll
    for (int p = 0; p < 4; p++) {
        ra[p] = *(const float4*)(Ag + (long)(p * 32) * lda);
        rb[p] = *(const float4*)(Bg + (long)(p * 32) * ldb);
    }
    stage(0);
    __syncthreads();

    float acc[2][8][4];
    #pragma unroll
    for (int mt = 0; mt < 2; mt++)
        #pragma unroll
        for (int nt = 0; nt < 8; nt++)
            #pragma unroll
            for (int i = 0; i < 4; i++) acc[mt][nt][i] = 0.0f;

    const int nIter = K >> 5;
    for (int it = 0; it < nIter; ++it) {
        const int cur = it & 1;
        if (it + 1 < nIter) {
            const float* pa = Ag + (it + 1) * 32;
            const float* pb = Bg + (it + 1) * 32;
            #pragma unroll
            for (int p = 0; p < 4; p++) {
                ra[p] = *(const float4*)(pa + (long)(p * 32) * lda);
                rb[p] = *(const float4*)(pb + (long)(p * 32) * ldb);
            }
        }

        const float* cAh = smAhi + cur * ABUF;
        const float* cAl = smAlo + cur * ABUF;
        const float* cBh = smBhi + cur * ABUF;
        const float* cBl = smBlo + cur * ABUF;

        #pragma unroll
        for (int kk = 0; kk < 32; kk += 8) {
            uint32_t ah[2][4], al[2][4], bh[8][2], bl[8][2];
            #pragma unroll
            for (int mt = 0; mt < 2; mt++) {
                int r = m_off + mt * 16 + lr;
                int o0 = r * SMEM_STRIDE + kk + lc;
                int o1 = (r + 8) * SMEM_STRIDE + kk + lc;
                ah[mt][0] = __float_as_uint(cAh[o0]);
                ah[mt][1] = __float_as_uint(cAh[o1]);
                ah[mt][2] = __float_as_uint(cAh[o0 + 4]);
                ah[mt][3] = __float_as_uint(cAh[o1 + 4]);
                al[mt][0] = __float_as_uint(cAl[o0]);
                al[mt][1] = __float_as_uint(cAl[o1]);
                al[mt][2] = __float_as_uint(cAl[o0 + 4]);
                al[mt][3] = __float_as_uint(cAl[o1 + 4]);
            }
            #pragma unroll
            for (int nt = 0; nt < 8; nt++) {
                int o = (n_off + nt * 8 + lr) * SMEM_STRIDE + kk + lc;
                bh[nt][0] = __float_as_uint(cBh[o]);
                bh[nt][1] = __float_as_uint(cBh[o + 4]);
                bl[nt][0] = __float_as_uint(cBl[o]);
                bl[nt][1] = __float_as_uint(cBl[o + 4]);
            }
            #pragma unroll
            for (int mt = 0; mt < 2; mt++)
                #pragma unroll
                for (int nt = 0; nt < 8; nt++) {
                    asm volatile(
                        "mma.sync.aligned.m16n8k8.row.col.f32.tf32.tf32.f32 "
                        "{%0,%1,%2,%3}, {%4,%5,%6,%7}, {%8,%9}, {%0,%1,%2,%3};"
                        : "+f"(acc[mt][nt][0]), "+f"(acc[mt][nt][1]),
                          "+f"(acc[mt][nt][2]), "+f"(acc[mt][nt][3])
                        : "r"(ah[mt][0]), "r"(ah[mt][1]), "r"(ah[mt][2]), "r"(ah[mt][3]),
                          "r"(bh[nt][0]), "r"(bh[nt][1]));
                    asm volatile(
                        "mma.sync.aligned.m16n8k8.row.col.f32.tf32.tf32.f32 "
                        "{%0,%1,%2,%3}, {%4,%5,%6,%7}, {%8,%9}, {%0,%1,%2,%3};"
                        : "+f"(acc[mt][nt][0]), "+f"(acc[mt][nt][1]),
                          "+f"(acc[mt][nt][2]), "+f"(acc[mt][nt][3])
                        : "r"(ah[mt][0]), "r"(ah[mt][1]), "r"(ah[mt][2]), "r"(ah[mt][3]),
                          "r"(bl[nt][0]), "r"(bl[nt][1]));
                    asm volatile(
                        "mma.sync.aligned.m16n8k8.row.col.f32.tf32.tf32.f32 "
                        "{%0,%1,%2,%3}, {%4,%5,%6,%7}, {%8,%9}, {%0,%1,%2,%3};"
                        : "+f"(acc[mt][nt][0]), "+f"(acc[mt][nt][1]),
                          "+f"(acc[mt][nt][2]), "+f"(acc[mt][nt][3])
                        : "r"(al[mt][0]), "r"(al[mt][1]), "r"(al[mt][2]), "r"(al[mt][3]),
                          "r"(bh[nt][0]), "r"(bh[nt][1]));
                }
        }

        if (it + 1 < nIter) {
            // stage into the other buffer
            const int nxt = cur ^ 1;
            float4 sa[4], sb[4];
            #pragma unroll
            for (int p = 0; p < 4; p++) { sa[p] = ra[p]; sb[p] = rb[p]; }
            (void)sa; (void)sb;
            stage(nxt);
        }
        __syncthreads();
    }

    // epilogue
    #pragma unroll
    for (int mt = 0; mt < 2; mt++) {
        #pragma unroll
        for (int nt = 0; nt < 8; nt++) {
            int r0 = row0 + m_off + mt * 16 + lr;
            int cc = col0 + n_off + nt * 8 + lc * 2;
            float2 v0, v1;
            v0.x = acc[mt][nt][0] * alpha;
            v0.y = acc[mt][nt][1] * alpha;
            v1.x = acc[mt][nt][2] * alpha;
            v1.y = acc[mt][nt][3] * alpha;
            if (BIAS) {
                v0.x += bias[cc]; v0.y += bias[cc + 1];
                v1.x += bias[cc]; v1.y += bias[cc + 1];
            }
            *(float2*)(C + (long)r0 * ldc + cc)       = v0;
            *(float2*)(C + (long)(r0 + 8) * ldc + cc) = v1;
        }
    }
}

// ---------------------------------------------------------------------------
// Fused per-head RMSNorm + RoPE (one warp per (s,h) row of 128)
// ---------------------------------------------------------------------------
__global__ __launch_bounds__(128) void norm_rope_kernel(
    float* __restrict__ x,
    const float* __restrict__ g_img,
    const float* __restrict__ g_txt,
    const float* __restrict__ freqs)
{
    int r = blockIdx.x * 4 + (threadIdx.x >> 5);
    int lane = threadIdx.x & 31;
    int s = r / NHEADS;

    float* p = x + (long)r * DHEAD + lane * 4;
    float4 v = *(const float4*)p;

    float ss = v.x * v.x + v.y * v.y + v.z * v.z + v.w * v.w;
    #pragma unroll
    for (int o = 16; o; o >>= 1) ss += __shfl_xor_sync(0xffffffffu, ss, o);
    float rn = rsqrtf(ss * (1.0f / 128.0f) + 1e-5f);

    const float* g = (s < SEQ_TXT) ? g_txt : g_img;
    int d = lane * 4;
    float x0 = v.x * rn * g[d + 0];
    float x1 = v.y * rn * g[d + 1];
    float x2 = v.z * rn * g[d + 2];
    float x3 = v.w * rn * g[d + 3];

    const float* f = freqs + (long)s * 256 + (d / 2) * 4;
    float4 o;
    o.x = f[0] * x0 + f[1] * x1;
    o.y = f[2] * x0 + f[3] * x1;
    o.z = f[4] * x2 + f[5] * x3;
    o.w = f[6] * x2 + f[7] * x3;
    *(float4*)p = o;
}

// ---------------------------------------------------------------------------
// Row softmax over 2304 elements
// ---------------------------------------------------------------------------
__global__ __launch_bounds__(256) void softmax_kernel(float* __restrict__ S)
{
    long row = blockIdx.x;
    float* p = S + row * 2304;
    int tid = threadIdx.x;

    float v[9];
    float mx = -INFINITY;
    #pragma unroll
    for (int i = 0; i < 9; i++) {
        v[i] = p[tid + i * 256];
        mx = fmaxf(mx, v[i]);
    }

    __shared__ float red[8];
    #pragma unroll
    for (int o = 16; o; o >>= 1) mx = fmaxf(mx, __shfl_xor_sync(0xffffffffu, mx, o));
    if ((tid & 31) == 0) red[tid >> 5] = mx;
    __syncthreads();
    float m = red[0];
    #pragma unroll
    for (int i = 1; i < 8; i++) m = fmaxf(m, red[i]);
    __syncthreads();

    float sum = 0.0f;
    #pragma unroll
    for (int i = 0; i < 9; i++) {
        v[i] = __expf(v[i] - m);
        sum += v[i];
    }
    #pragma unroll
    for (int o = 16; o; o >>= 1) sum += __shfl_xor_sync(0xffffffffu, sum, o);
    if ((tid & 31) == 0) red[tid >> 5] = sum;
    __syncthreads();
    float tot = 0.0f;
    #pragma unroll
    for (int i = 0; i < 8; i++) tot += red[i];
    float inv = 1.0f / tot;

    #pragma unroll
    for (int i = 0; i < 9; i++) p[tid + i * 256] = v[i] * inv;
}

// ---------------------------------------------------------------------------
extern "C" void kernel_launch(void* const* d_in, const int* in_sizes, int n_in,
                              void* d_out, int out_size)
{
    const float* hid   = (const float*)d_in[0];
    const float* enc   = (const float*)d_in[1];
    const float* freqs = (const float*)d_in[2];
    const float* W[8]  = { (const float*)d_in[3],  (const float*)d_in[4],
                           (const float*)d_in[5],  (const float*)d_in[6],
                           (const float*)d_in[7],  (const float*)d_in[8],
                           (const float*)d_in[13], (const float*)d_in[15] };
    const float* gq  = (const float*)d_in[9];
    const float* gk  = (const float*)d_in[10];
    const float* gaq = (const float*)d_in[11];
    const float* gak = (const float*)d_in[12];
    const float* bo  = (const float*)d_in[14];
    const float* bao = (const float*)d_in[16];
    float* out = (float*)d_out;

    float *q, *k, *v, *attn, *sc, *vt, *wt;
    cudaGetSymbolAddress((void**)&q,    g_q);
    cudaGetSymbolAddress((void**)&k,    g_k);
    cudaGetSymbolAddress((void**)&v,    g_v);
    cudaGetSymbolAddress((void**)&attn, g_attn);
    cudaGetSymbolAddress((void**)&sc,   g_s);
    cudaGetSymbolAddress((void**)&vt,   g_vt);
    cudaGetSymbolAddress((void**)&wt,   g_wt);

    cudaFuncSetAttribute(tgemm<false>, cudaFuncAttributeMaxDynamicSharedMemorySize, SMEMB_TOTAL);
    cudaFuncSetAttribute(tgemm<true>,  cudaFuncAttributeMaxDynamicSharedMemorySize, SMEMB_TOTAL);

    dim3 blk(256);
    const long WSZ = (long)DMODEL * DMODEL;

    // --- transpose all weights: wt[i][n][k] = W[i][k][n] ---
    for (int i = 0; i < 8; i++)
        transpose_kernel<<<dim3(96, 96), dim3(32, 8)>>>(W[i], wt + i * WSZ, DMODEL, DMODEL);

    // --- QKV projections (txt rows 0..255, img rows 256..2303) ---
    // W[]: 0=Wq 1=Wk 2=Wv 3=Waq 4=Wak 5=Wav 6=Wo 7=Wao
    float* dst[3] = { q, k, v };
    for (int i = 0; i < 3; i++) {
        tgemm<false><<<dim3(24, 2, 1), blk, SMEMB_TOTAL>>>(
            enc, DMODEL, 0, wt + (3 + i) * WSZ, DMODEL, 0,
            dst[i], DMODEL, 0, DMODEL, nullptr, 1.0f);
        tgemm<false><<<dim3(24, 16, 1), blk, SMEMB_TOTAL>>>(
            hid, DMODEL, 0, wt + i * WSZ, DMODEL, 0,
            dst[i] + (long)SEQ_TXT * DMODEL, DMODEL, 0, DMODEL, nullptr, 1.0f);
    }

    // --- RMSNorm + RoPE on q and k ---
    norm_rope_kernel<<<SEQ_TOT * NHEADS / 4, 128>>>(q, gq, gaq, freqs);
    norm_rope_kernel<<<SEQ_TOT * NHEADS / 4, 128>>>(k, gk, gak, freqs);

    // --- transpose V: vt[d_full][s] = v[s][d_full] ---
    transpose_kernel<<<dim3(96, 72), dim3(32, 8)>>>(v, vt, SEQ_TOT, DMODEL);

    // --- Scores: S_h = scale * Q_h @ K_h^T ---
    const float scale = 0.088388347648318447f;  // 1/sqrt(128)
    tgemm<false><<<dim3(18, 18, 24), blk, SMEMB_TOTAL>>>(
        q, DMODEL, 128, k, DMODEL, 128, sc, 2304, SS, DHEAD, nullptr, scale);

    // --- Softmax ---
    softmax_kernel<<<NHEADS * SEQ_TOT, 256>>>(sc);

    // --- PV: attn_h = P_h @ V_h  (B = vt per head, NT) ---
    tgemm<false><<<dim3(1, 18, 24), blk, SMEMB_TOTAL>>>(
        sc, 2304, SS, vt, SEQ_TOT, (long)DHEAD * SEQ_TOT,
        attn, DMODEL, 128, SEQ_TOT, nullptr, 1.0f);

    // --- Output projections (img first, then txt) ---
    tgemm<true><<<dim3(24, 16, 1), blk, SMEMB_TOTAL>>>(
        attn + (long)SEQ_TXT * DMODEL, DMODEL, 0, wt + 6 * WSZ, DMODEL, 0,
        out, DMODEL, 0, DMODEL, bo, 1.0f);
    tgemm<true><<<dim3(24, 2, 1), blk, SMEMB_TOTAL>>>(
        attn, DMODEL, 0, wt + 7 * WSZ, DMODEL, 0,
        out + (long)SEQ_IMG * DMODEL, DMODEL, 0, DMODEL, bao, 1.0f);
}

// round 5
// speedup vs baseline: 2.5450x; 1.3526x over previous
#include <cuda_runtime.h>
#include <cuda_bf16.h>
#include <math.h>
#include <stdint.h>

// Problem constants
#define SEQ_TXT 256
#define SEQ_IMG 2048
#define SEQ_TOT 2304
#define DMODEL  3072
#define NHEADS  24
#define DHEAD   128
#define SS      (2304LL*2304LL)

// Scratch
__device__ float g_q[SEQ_TOT * DMODEL];
__device__ float g_k[SEQ_TOT * DMODEL];
__device__ float g_v[SEQ_TOT * DMODEL];
__device__ float g_attn[SEQ_TOT * DMODEL];
__device__ float g_vt[DMODEL * SEQ_TOT];
__device__ float g_wt[8][DMODEL * (long)DMODEL];
__device__ float g_s[24LL * 2304LL * 2304LL];

// ---------------------------------------------------------------------------
// bf16x4 tensor-core GEMM: C = alpha * A @ B^T (+bias), near-fp32 accuracy.
// Each operand split x = hi + lo (both bf16); all 4 cross terms accumulated
// with mma.sync.m16n8k16.bf16 into fp32.
// A: M x K row-major. B: N x K row-major ("NT").
// Tiles 128x128x32, 8 warps (32x64 each), double-buffered smem.
// Smem rows: 32 bf16 = 16 words, padded to 20-word stride (conflict-free).
// ---------------------------------------------------------------------------
#define WSTRIDE 20
#define TILE_WORDS (128 * WSTRIDE)          // one matrix-half tile (words)
#define STAGE_WORDS (4 * TILE_WORDS)        // Ahi,Alo,Bhi,Blo
#define SMEMB_TOTAL (2 * STAGE_WORDS * 4)   // bytes, 2 stages = 81920

template<bool BIAS>
__global__ __launch_bounds__(256) void tgemm(
    const float* __restrict__ A, int lda, long sA,
    const float* __restrict__ B, int ldb, long sB,
    float*       __restrict__ C, int ldc, long sC,
    int K, const float* __restrict__ bias, float alpha)
{
    extern __shared__ uint32_t sm[];
    uint32_t* smAhi = sm;
    uint32_t* smAlo = sm + 2 * TILE_WORDS;   // [2 stages] interleave below
    uint32_t* smBhi = sm + 4 * TILE_WORDS;
    uint32_t* smBlo = sm + 6 * TILE_WORDS;
    // stage s of X lives at smX + s*TILE_WORDS

    const int bz = blockIdx.z;
    A += (long)bz * sA;
    B += (long)bz * sB;
    C += (long)bz * sC;

    const int row0 = blockIdx.y * 128;
    const int col0 = blockIdx.x * 128;

    const int tid  = threadIdx.x;
    const int lane = tid & 31;
    const int wid  = tid >> 5;
    const int m_off = (wid & 3) * 32;
    const int n_off = (wid >> 2) * 64;
    const int lr = lane >> 2;
    const int lc = lane & 3;

    const int gr  = tid >> 3;         // 0..31
    const int gw2 = (tid & 7) * 2;    // word col 0,2,..,14
    const float* Ag = A + (long)(row0 + gr) * lda + gw2 * 2;
    const float* Bg = B + (long)(col0 + gr) * ldb + gw2 * 2;

    float4 ra[4], rb[4];

    auto split_pack = [] (float x, float y, uint32_t& hi, uint32_t& lo) {
        __nv_bfloat16 hx = __float2bfloat16_rn(x);
        __nv_bfloat16 hy = __float2bfloat16_rn(y);
        float lx = x - __bfloat162float(hx);
        float ly = y - __bfloat162float(hy);
        __nv_bfloat162 h2 = __halves2bfloat162(hx, hy);     // x -> low
        __nv_bfloat162 l2 = __floats2bfloat162_rn(lx, ly);  // lx -> low
        hi = *(uint32_t*)&h2;
        lo = *(uint32_t*)&l2;
    };

    auto stage = [&](int buf) {
        uint32_t* dAh = smAhi + buf * TILE_WORDS;
        uint32_t* dAl = smAlo + buf * TILE_WORDS;
        uint32_t* dBh = smBhi + buf * TILE_WORDS;
        uint32_t* dBl = smBlo + buf * TILE_WORDS;
        #pragma unroll
        for (int p = 0; p < 4; p++) {
            int off = (gr + p * 32) * WSTRIDE + gw2;
            uint32_t h0, h1, l0, l1;
            split_pack(ra[p].x, ra[p].y, h0, l0);
            split_pack(ra[p].z, ra[p].w, h1, l1);
            *(uint2*)(dAh + off) = make_uint2(h0, h1);
            *(uint2*)(dAl + off) = make_uint2(l0, l1);
            split_pack(rb[p].x, rb[p].y, h0, l0);
            split_pack(rb[p].z, rb[p].w, h1, l1);
            *(uint2*)(dBh + off) = make_uint2(h0, h1);
            *(uint2*)(dBl + off) = make_uint2(l0, l1);
        }
    };

    // preload k-tile 0
    #pragma unroll
    for (int p = 0; p < 4; p++) {
        ra[p] = *(const float4*)(Ag + (long)(p * 32) * lda);
        rb[p] = *(const float4*)(Bg + (long)(p * 32) * ldb);
    }
    stage(0);
    __syncthreads();

    float acc[2][8][4];
    #pragma unroll
    for (int mt = 0; mt < 2; mt++)
        #pragma unroll
        for (int nt = 0; nt < 8; nt++)
            #pragma unroll
            for (int i = 0; i < 4; i++) acc[mt][nt][i] = 0.0f;

    const int nIter = K >> 5;
    for (int it = 0; it < nIter; ++it) {
        const int cur = it & 1;
        if (it + 1 < nIter) {
            const float* pa = Ag + (it + 1) * 32;
            const float* pb = Bg + (it + 1) * 32;
            #pragma unroll
            for (int p = 0; p < 4; p++) {
                ra[p] = *(const float4*)(pa + (long)(p * 32) * lda);
                rb[p] = *(const float4*)(pb + (long)(p * 32) * ldb);
            }
        }

        const uint32_t* cAh = smAhi + cur * TILE_WORDS;
        const uint32_t* cAl = smAlo + cur * TILE_WORDS;
        const uint32_t* cBh = smBhi + cur * TILE_WORDS;
        const uint32_t* cBl = smBlo + cur * TILE_WORDS;

        #pragma unroll
        for (int ks = 0; ks < 2; ks++) {           // two k16 steps per chunk
            uint32_t ah[2][4], al[2][4], bh[8][2], bl[8][2];
            #pragma unroll
            for (int mt = 0; mt < 2; mt++) {
                int r = m_off + mt * 16 + lr;
                int o0 = r * WSTRIDE + ks * 8 + lc;
                int o1 = (r + 8) * WSTRIDE + ks * 8 + lc;
                ah[mt][0] = cAh[o0];     ah[mt][1] = cAh[o1];
                ah[mt][2] = cAh[o0 + 4]; ah[mt][3] = cAh[o1 + 4];
                al[mt][0] = cAl[o0];     al[mt][1] = cAl[o1];
                al[mt][2] = cAl[o0 + 4]; al[mt][3] = cAl[o1 + 4];
            }
            #pragma unroll
            for (int nt = 0; nt < 8; nt++) {
                int o = (n_off + nt * 8 + lr) * WSTRIDE + ks * 8 + lc;
                bh[nt][0] = cBh[o]; bh[nt][1] = cBh[o + 4];
                bl[nt][0] = cBl[o]; bl[nt][1] = cBl[o + 4];
            }
            #pragma unroll
            for (int mt = 0; mt < 2; mt++)
                #pragma unroll
                for (int nt = 0; nt < 8; nt++) {
                    float* c = acc[mt][nt];
                    #define MMA_BF16(AV, BV) \
                        asm volatile( \
                            "mma.sync.aligned.m16n8k16.row.col.f32.bf16.bf16.f32 " \
                            "{%0,%1,%2,%3}, {%4,%5,%6,%7}, {%8,%9}, {%0,%1,%2,%3};" \
                            : "+f"(c[0]), "+f"(c[1]), "+f"(c[2]), "+f"(c[3]) \
                            : "r"(AV[0]), "r"(AV[1]), "r"(AV[2]), "r"(AV[3]), \
                              "r"(BV[0]), "r"(BV[1]))
                    MMA_BF16(ah[mt], bh[nt]);
                    MMA_BF16(ah[mt], bl[nt]);
                    MMA_BF16(al[mt], bh[nt]);
                    MMA_BF16(al[mt], bl[nt]);
                    #undef MMA_BF16
                }
        }

        if (it + 1 < nIter) stage(cur ^ 1);
        __syncthreads();
    }

    // epilogue
    #pragma unroll
    for (int mt = 0; mt < 2; mt++) {
        #pragma unroll
        for (int nt = 0; nt < 8; nt++) {
            int r0 = row0 + m_off + mt * 16 + lr;
            int cc = col0 + n_off + nt * 8 + lc * 2;
            float2 v0, v1;
            v0.x = acc[mt][nt][0] * alpha;
            v0.y = acc[mt][nt][1] * alpha;
            v1.x = acc[mt][nt][2] * alpha;
            v1.y = acc[mt][nt][3] * alpha;
            if (BIAS) {
                v0.x += bias[cc]; v0.y += bias[cc + 1];
                v1.x += bias[cc]; v1.y += bias[cc + 1];
            }
            *(float2*)(C + (long)r0 * ldc + cc)       = v0;
            *(float2*)(C + (long)(r0 + 8) * ldc + cc) = v1;
        }
    }
}

// ---------------------------------------------------------------------------
// 32x32 tiled transpose
// ---------------------------------------------------------------------------
__global__ __launch_bounds__(256) void transpose_kernel(
    const float* __restrict__ in, float* __restrict__ out, int rows, int cols)
{
    __shared__ float t[32][33];
    int bx = blockIdx.x * 32;
    int by = blockIdx.y * 32;
    int x = bx + threadIdx.x;
    #pragma unroll
    for (int j = 0; j < 32; j += 8)
        t[threadIdx.y + j][threadIdx.x] = in[(long)(by + threadIdx.y + j) * cols + x];
    __syncthreads();
    int y = by + threadIdx.x;
    #pragma unroll
    for (int j = 0; j < 32; j += 8)
        out[(long)(bx + threadIdx.y + j) * rows + y] = t[threadIdx.x][threadIdx.y + j];
}

// ---------------------------------------------------------------------------
// RMSNorm + RoPE (one warp per (s,h) row of 128)
// ---------------------------------------------------------------------------
__global__ __launch_bounds__(128) void norm_rope_kernel(
    float* __restrict__ x,
    const float* __restrict__ g_img,
    const float* __restrict__ g_txt,
    const float* __restrict__ freqs)
{
    int r = blockIdx.x * 4 + (threadIdx.x >> 5);
    int lane = threadIdx.x & 31;
    int s = r / NHEADS;

    float* p = x + (long)r * DHEAD + lane * 4;
    float4 v = *(const float4*)p;

    float ss = v.x * v.x + v.y * v.y + v.z * v.z + v.w * v.w;
    #pragma unroll
    for (int o = 16; o; o >>= 1) ss += __shfl_xor_sync(0xffffffffu, ss, o);
    float rn = rsqrtf(ss * (1.0f / 128.0f) + 1e-5f);

    const float* g = (s < SEQ_TXT) ? g_txt : g_img;
    int d = lane * 4;
    float x0 = v.x * rn * g[d + 0];
    float x1 = v.y * rn * g[d + 1];
    float x2 = v.z * rn * g[d + 2];
    float x3 = v.w * rn * g[d + 3];

    const float* f = freqs + (long)s * 256 + (d / 2) * 4;
    float4 o;
    o.x = f[0] * x0 + f[1] * x1;
    o.y = f[2] * x0 + f[3] * x1;
    o.z = f[4] * x2 + f[5] * x3;
    o.w = f[6] * x2 + f[7] * x3;
    *(float4*)p = o;
}

// ---------------------------------------------------------------------------
// Row softmax over 2304 elements
// ---------------------------------------------------------------------------
__global__ __launch_bounds__(256) void softmax_kernel(float* __restrict__ S)
{
    long row = blockIdx.x;
    float* p = S + row * 2304;
    int tid = threadIdx.x;

    float v[9];
    float mx = -INFINITY;
    #pragma unroll
    for (int i = 0; i < 9; i++) {
        v[i] = p[tid + i * 256];
        mx = fmaxf(mx, v[i]);
    }

    __shared__ float red[8];
    #pragma unroll
    for (int o = 16; o; o >>= 1) mx = fmaxf(mx, __shfl_xor_sync(0xffffffffu, mx, o));
    if ((tid & 31) == 0) red[tid >> 5] = mx;
    __syncthreads();
    float m = red[0];
    #pragma unroll
    for (int i = 1; i < 8; i++) m = fmaxf(m, red[i]);
    __syncthreads();

    float sum = 0.0f;
    #pragma unroll
    for (int i = 0; i < 9; i++) {
        v[i] = __expf(v[i] - m);
        sum += v[i];
    }
    #pragma unroll
    for (int o = 16; o; o >>= 1) sum += __shfl_xor_sync(0xffffffffu, sum, o);
    if ((tid & 31) == 0) red[tid >> 5] = sum;
    __syncthreads();
    float tot = 0.0f;
    #pragma unroll
    for (int i = 0; i < 8; i++) tot += red[i];
    float inv = 1.0f / tot;

    #pragma unroll
    for (int i = 0; i < 9; i++) p[tid + i * 256] = v[i] * inv;
}

// ---------------------------------------------------------------------------
extern "C" void kernel_launch(void* const* d_in, const int* in_sizes, int n_in,
                              void* d_out, int out_size)
{
    const float* hid   = (const float*)d_in[0];
    const float* enc   = (const float*)d_in[1];
    const float* freqs = (const float*)d_in[2];
    const float* W[8]  = { (const float*)d_in[3],  (const float*)d_in[4],
                           (const float*)d_in[5],  (const float*)d_in[6],
                           (const float*)d_in[7],  (const float*)d_in[8],
                           (const float*)d_in[13], (const float*)d_in[15] };
    const float* gq  = (const float*)d_in[9];
    const float* gk  = (const float*)d_in[10];
    const float* gaq = (const float*)d_in[11];
    const float* gak = (const float*)d_in[12];
    const float* bo  = (const float*)d_in[14];
    const float* bao = (const float*)d_in[16];
    float* out = (float*)d_out;

    float *q, *k, *v, *attn, *sc, *vt, *wt;
    cudaGetSymbolAddress((void**)&q,    g_q);
    cudaGetSymbolAddress((void**)&k,    g_k);
    cudaGetSymbolAddress((void**)&v,    g_v);
    cudaGetSymbolAddress((void**)&attn, g_attn);
    cudaGetSymbolAddress((void**)&sc,   g_s);
    cudaGetSymbolAddress((void**)&vt,   g_vt);
    cudaGetSymbolAddress((void**)&wt,   g_wt);

    cudaFuncSetAttribute(tgemm<false>, cudaFuncAttributeMaxDynamicSharedMemorySize, SMEMB_TOTAL);
    cudaFuncSetAttribute(tgemm<true>,  cudaFuncAttributeMaxDynamicSharedMemorySize, SMEMB_TOTAL);

    dim3 blk(256);
    const long WSZ = (long)DMODEL * DMODEL;

    // transpose weights: wt[i][n][k] = W[i][k][n]
    for (int i = 0; i < 8; i++)
        transpose_kernel<<<dim3(96, 96), dim3(32, 8)>>>(W[i], wt + i * WSZ, DMODEL, DMODEL);

    // QKV projections. W[]: 0=Wq 1=Wk 2=Wv 3=Waq 4=Wak 5=Wav 6=Wo 7=Wao
    float* dst[3] = { q, k, v };
    for (int i = 0; i < 3; i++) {
        tgemm<false><<<dim3(24, 2, 1), blk, SMEMB_TOTAL>>>(
            enc, DMODEL, 0, wt + (3 + i) * WSZ, DMODEL, 0,
            dst[i], DMODEL, 0, DMODEL, nullptr, 1.0f);
        tgemm<false><<<dim3(24, 16, 1), blk, SMEMB_TOTAL>>>(
            hid, DMODEL, 0, wt + i * WSZ, DMODEL, 0,
            dst[i] + (long)SEQ_TXT * DMODEL, DMODEL, 0, DMODEL, nullptr, 1.0f);
    }

    // RMSNorm + RoPE
    norm_rope_kernel<<<SEQ_TOT * NHEADS / 4, 128>>>(q, gq, gaq, freqs);
    norm_rope_kernel<<<SEQ_TOT * NHEADS / 4, 128>>>(k, gk, gak, freqs);

    // transpose V
    transpose_kernel<<<dim3(96, 72), dim3(32, 8)>>>(v, vt, SEQ_TOT, DMODEL);

    // Scores: S_h = scale * Q_h @ K_h^T
    const float scale = 0.088388347648318447f;
    tgemm<false><<<dim3(18, 18, 24), blk, SMEMB_TOTAL>>>(
        q, DMODEL, 128, k, DMODEL, 128, sc, 2304, SS, DHEAD, nullptr, scale);

    // Softmax
    softmax_kernel<<<NHEADS * SEQ_TOT, 256>>>(sc);

    // PV: attn_h = P_h @ V_h  (B = vt per head, NT)
    tgemm<false><<<dim3(1, 18, 24), blk, SMEMB_TOTAL>>>(
        sc, 2304, SS, vt, SEQ_TOT, (long)DHEAD * SEQ_TOT,
        attn, DMODEL, 128, SEQ_TOT, nullptr, 1.0f);

    // Output projections (img first, then txt)
    tgemm<true><<<dim3(24, 16, 1), blk, SMEMB_TOTAL>>>(
        attn + (long)SEQ_TXT * DMODEL, DMODEL, 0, wt + 6 * WSZ, DMODEL, 0,
        out, DMODEL, 0, DMODEL, bo, 1.0f);
    tgemm<true><<<dim3(24, 2, 1), blk, SMEMB_TOTAL>>>(
        attn, DMODEL, 0, wt + 7 * WSZ, DMODEL, 0,
        out + (long)SEQ_IMG * DMODEL, DMODEL, 0, DMODEL, bao, 1.0f);
}

// round 6
// speedup vs baseline: 2.9451x; 1.1572x over previous
#include <cuda_runtime.h>
#include <cuda_bf16.h>
#include <math.h>
#include <stdint.h>

// Problem constants
#define SEQ_TXT 256
#define SEQ_IMG 2048
#define SEQ_TOT 2304
#define DMODEL  3072
#define NHEADS  24
#define DHEAD   128
#define SS      (2304LL*2304LL)

typedef __nv_bfloat16 bf16;

// fp32 scratch
__device__ float g_q[SEQ_TOT * DMODEL];
__device__ float g_k[SEQ_TOT * DMODEL];
__device__ float g_v[SEQ_TOT * DMODEL];
__device__ float g_attn[SEQ_TOT * DMODEL];
__device__ float g_s[24LL * 2304LL * 2304LL];

// bf16 hi/lo pre-split operands
__device__ bf16 g_xh[SEQ_TOT * DMODEL],  g_xl[SEQ_TOT * DMODEL];    // [enc;hid]
__device__ bf16 g_qh[SEQ_TOT * DMODEL],  g_ql[SEQ_TOT * DMODEL];
__device__ bf16 g_kh[SEQ_TOT * DMODEL],  g_kl[SEQ_TOT * DMODEL];
__device__ bf16 g_vth[DMODEL * SEQ_TOT], g_vtl[DMODEL * SEQ_TOT];
__device__ bf16 g_ath[SEQ_TOT * DMODEL], g_atl[SEQ_TOT * DMODEL];   // attn split
__device__ bf16 g_wth[8][DMODEL * (long)DMODEL];
__device__ bf16 g_wtl[8][DMODEL * (long)DMODEL];

__device__ __forceinline__ void bsplit(float x, bf16& h, bf16& l) {
    h = __float2bfloat16_rn(x);
    l = __float2bfloat16_rn(x - __bfloat162float(h));
}
__device__ __forceinline__ uint32_t pack2(bf16 a, bf16 b) {
    __nv_bfloat162 t = __halves2bfloat162(a, b);
    return *(uint32_t*)&t;
}

// ---------------------------------------------------------------------------
// bf16x3 tensor-core GEMM: C = alpha * A @ B^T (+bias).
// B always pre-split bf16 (hi/lo, row-major N x K).
// A pre-split (PSA=true) or fp32 split-on-load (PSA=false).
// Tiles 128x128x32, 8 warps (32x64 each), double-buffered smem,
// row stride 20 words (conflict-free fragment loads).
// ---------------------------------------------------------------------------
#define WSTRIDE 20
#define TILE_WORDS (128 * WSTRIDE)
#define SMEMB_TOTAL (8 * TILE_WORDS * 4)   // 81920 bytes

template<bool PSA, bool BIAS>
__global__ __launch_bounds__(256) void tgemm(
    const float* __restrict__ A,
    const bf16* __restrict__ Ahi, const bf16* __restrict__ Alo,
    int lda, long sA,
    const bf16* __restrict__ Bhi, const bf16* __restrict__ Blo,
    int ldb, long sB,
    float* __restrict__ C, int ldc, long sC,
    int K, const float* __restrict__ bias, float alpha)
{
    extern __shared__ uint32_t sm[];
    uint32_t* smAhi = sm;
    uint32_t* smAlo = sm + 2 * TILE_WORDS;
    uint32_t* smBhi = sm + 4 * TILE_WORDS;
    uint32_t* smBlo = sm + 6 * TILE_WORDS;

    const int bz = blockIdx.z;
    if (PSA) { Ahi += (long)bz * sA; Alo += (long)bz * sA; }
    else     { A   += (long)bz * sA; }
    Bhi += (long)bz * sB; Blo += (long)bz * sB;
    C   += (long)bz * sC;

    const int row0 = blockIdx.y * 128;
    const int col0 = blockIdx.x * 128;

    const int tid  = threadIdx.x;
    const int lane = tid & 31;
    const int wid  = tid >> 5;
    const int m_off = (wid & 3) * 32;
    const int n_off = (wid >> 2) * 64;
    const int lr = lane >> 2;
    const int lc = lane & 3;

    // pre-split loader mapping: 4 threads/row, 8 bf16 each, 64 rows/pass
    const int pr = tid >> 2;
    const int pw = (tid & 3) * 4;       // word col
    // fp32 loader mapping: 8 threads/row, 4 floats each, 32 rows/pass
    const int gr  = tid >> 3;
    const int gw2 = (tid & 7) * 2;      // word col

    uint4 rah[2], ral[2], rbh[2], rbl[2];
    float4 raf[4];

    auto gload = [&](int k0) {
        if (PSA) {
            #pragma unroll
            for (int p = 0; p < 2; p++) {
                long ro = (long)(row0 + pr + p * 64) * lda + k0 + pw * 2;
                rah[p] = *(const uint4*)(Ahi + ro);
                ral[p] = *(const uint4*)(Alo + ro);
            }
        } else {
            #pragma unroll
            for (int p = 0; p < 4; p++)
                raf[p] = *(const float4*)(A + (long)(row0 + gr + p * 32) * lda + k0 + gw2 * 2);
        }
        #pragma unroll
        for (int p = 0; p < 2; p++) {
            long ro = (long)(col0 + pr + p * 64) * ldb + k0 + pw * 2;
            rbh[p] = *(const uint4*)(Bhi + ro);
            rbl[p] = *(const uint4*)(Blo + ro);
        }
    };

    auto stage = [&](int buf) {
        uint32_t* dAh = smAhi + buf * TILE_WORDS;
        uint32_t* dAl = smAlo + buf * TILE_WORDS;
        uint32_t* dBh = smBhi + buf * TILE_WORDS;
        uint32_t* dBl = smBlo + buf * TILE_WORDS;
        if (PSA) {
            #pragma unroll
            for (int p = 0; p < 2; p++) {
                int off = (pr + p * 64) * WSTRIDE + pw;
                *(uint4*)(dAh + off) = rah[p];
                *(uint4*)(dAl + off) = ral[p];
            }
        } else {
            #pragma unroll
            for (int p = 0; p < 4; p++) {
                int off = (gr + p * 32) * WSTRIDE + gw2;
                bf16 h0, l0, h1, l1, h2, l2, h3, l3;
                bsplit(raf[p].x, h0, l0); bsplit(raf[p].y, h1, l1);
                bsplit(raf[p].z, h2, l2); bsplit(raf[p].w, h3, l3);
                *(uint2*)(dAh + off) = make_uint2(pack2(h0, h1), pack2(h2, h3));
                *(uint2*)(dAl + off) = make_uint2(pack2(l0, l1), pack2(l2, l3));
            }
        }
        #pragma unroll
        for (int p = 0; p < 2; p++) {
            int off = (pr + p * 64) * WSTRIDE + pw;
            *(uint4*)(dBh + off) = rbh[p];
            *(uint4*)(dBl + off) = rbl[p];
        }
    };

    gload(0);
    stage(0);
    __syncthreads();

    float acc[2][8][4];
    #pragma unroll
    for (int mt = 0; mt < 2; mt++)
        #pragma unroll
        for (int nt = 0; nt < 8; nt++)
            #pragma unroll
            for (int i = 0; i < 4; i++) acc[mt][nt][i] = 0.0f;

    const int nIter = K >> 5;
    for (int it = 0; it < nIter; ++it) {
        const int cur = it & 1;
        if (it + 1 < nIter) gload((it + 1) * 32);

        const uint32_t* cAh = smAhi + cur * TILE_WORDS;
        const uint32_t* cAl = smAlo + cur * TILE_WORDS;
        const uint32_t* cBh = smBhi + cur * TILE_WORDS;
        const uint32_t* cBl = smBlo + cur * TILE_WORDS;

        #pragma unroll
        for (int ks = 0; ks < 2; ks++) {
            uint32_t ah[2][4], al[2][4], bh[8][2], bl[8][2];
            #pragma unroll
            for (int mt = 0; mt < 2; mt++) {
                int r = m_off + mt * 16 + lr;
                int o0 = r * WSTRIDE + ks * 8 + lc;
                int o1 = (r + 8) * WSTRIDE + ks * 8 + lc;
                ah[mt][0] = cAh[o0];     ah[mt][1] = cAh[o1];
                ah[mt][2] = cAh[o0 + 4]; ah[mt][3] = cAh[o1 + 4];
                al[mt][0] = cAl[o0];     al[mt][1] = cAl[o1];
                al[mt][2] = cAl[o0 + 4]; al[mt][3] = cAl[o1 + 4];
            }
            #pragma unroll
            for (int nt = 0; nt < 8; nt++) {
                int o = (n_off + nt * 8 + lr) * WSTRIDE + ks * 8 + lc;
                bh[nt][0] = cBh[o]; bh[nt][1] = cBh[o + 4];
                bl[nt][0] = cBl[o]; bl[nt][1] = cBl[o + 4];
            }
            #pragma unroll
            for (int mt = 0; mt < 2; mt++)
                #pragma unroll
                for (int nt = 0; nt < 8; nt++) {
                    float* c = acc[mt][nt];
                    #define MMA_BF16(AV, BV) \
                        asm volatile( \
                            "mma.sync.aligned.m16n8k16.row.col.f32.bf16.bf16.f32 " \
                            "{%0,%1,%2,%3}, {%4,%5,%6,%7}, {%8,%9}, {%0,%1,%2,%3};" \
                            : "+f"(c[0]), "+f"(c[1]), "+f"(c[2]), "+f"(c[3]) \
                            : "r"(AV[0]), "r"(AV[1]), "r"(AV[2]), "r"(AV[3]), \
                              "r"(BV[0]), "r"(BV[1]))
                    MMA_BF16(ah[mt], bh[nt]);
                    MMA_BF16(ah[mt], bl[nt]);
                    MMA_BF16(al[mt], bh[nt]);
                    #undef MMA_BF16
                }
        }

        if (it + 1 < nIter) stage(cur ^ 1);
        __syncthreads();
    }

    // epilogue
    #pragma unroll
    for (int mt = 0; mt < 2; mt++) {
        #pragma unroll
        for (int nt = 0; nt < 8; nt++) {
            int r0 = row0 + m_off + mt * 16 + lr;
            int cc = col0 + n_off + nt * 8 + lc * 2;
            float2 v0, v1;
            v0.x = acc[mt][nt][0] * alpha;
            v0.y = acc[mt][nt][1] * alpha;
            v1.x = acc[mt][nt][2] * alpha;
            v1.y = acc[mt][nt][3] * alpha;
            if (BIAS) {
                v0.x += bias[cc]; v0.y += bias[cc + 1];
                v1.x += bias[cc]; v1.y += bias[cc + 1];
            }
            *(float2*)(C + (long)r0 * ldc + cc)       = v0;
            *(float2*)(C + (long)(r0 + 8) * ldc + cc) = v1;
        }
    }
}

// ---------------------------------------------------------------------------
// elementwise split: fp32 -> bf16 hi/lo
// ---------------------------------------------------------------------------
__global__ __launch_bounds__(256) void split_kernel(
    const float* __restrict__ in, bf16* __restrict__ hi, bf16* __restrict__ lo, int n4)
{
    int idx = blockIdx.x * 256 + threadIdx.x;
    if (idx >= n4) return;
    float4 v = ((const float4*)in)[idx];
    bf16 h0, l0, h1, l1, h2, l2, h3, l3;
    bsplit(v.x, h0, l0); bsplit(v.y, h1, l1);
    bsplit(v.z, h2, l2); bsplit(v.w, h3, l3);
    ((uint2*)hi)[idx] = make_uint2(pack2(h0, h1), pack2(h2, h3));
    ((uint2*)lo)[idx] = make_uint2(pack2(l0, l1), pack2(l2, l3));
}

// ---------------------------------------------------------------------------
// 32x32 tiled transpose + split: out_hi/lo[c][r] = split(in[r][c])
// ---------------------------------------------------------------------------
__global__ __launch_bounds__(256) void transpose_split_kernel(
    const float* __restrict__ in, bf16* __restrict__ hi, bf16* __restrict__ lo,
    int rows, int cols)
{
    __shared__ float t[32][33];
    int bx = blockIdx.x * 32;
    int by = blockIdx.y * 32;
    int x = bx + threadIdx.x;
    #pragma unroll
    for (int j = 0; j < 32; j += 8)
        t[threadIdx.y + j][threadIdx.x] = in[(long)(by + threadIdx.y + j) * cols + x];
    __syncthreads();
    int y = by + threadIdx.x;
    #pragma unroll
    for (int j = 0; j < 32; j += 8) {
        float val = t[threadIdx.x][threadIdx.y + j];
        bf16 h, l;
        bsplit(val, h, l);
        long o = (long)(bx + threadIdx.y + j) * rows + y;
        hi[o] = h; lo[o] = l;
    }
}

// ---------------------------------------------------------------------------
// RMSNorm + RoPE, output split to bf16 hi/lo (one warp per (s,h) row)
// ---------------------------------------------------------------------------
__global__ __launch_bounds__(128) void norm_rope_split_kernel(
    const float* __restrict__ x,
    bf16* __restrict__ oh, bf16* __restrict__ ol,
    const float* __restrict__ g_im,
    const float* __restrict__ g_tx,
    const float* __restrict__ freqs)
{
    int r = blockIdx.x * 4 + (threadIdx.x >> 5);
    int lane = threadIdx.x & 31;
    int s = r / NHEADS;

    const float* p = x + (long)r * DHEAD + lane * 4;
    float4 v = *(const float4*)p;

    float ss = v.x * v.x + v.y * v.y + v.z * v.z + v.w * v.w;
    #pragma unroll
    for (int o = 16; o; o >>= 1) ss += __shfl_xor_sync(0xffffffffu, ss, o);
    float rn = rsqrtf(ss * (1.0f / 128.0f) + 1e-5f);

    const float* g = (s < SEQ_TXT) ? g_tx : g_im;
    int d = lane * 4;
    float x0 = v.x * rn * g[d + 0];
    float x1 = v.y * rn * g[d + 1];
    float x2 = v.z * rn * g[d + 2];
    float x3 = v.w * rn * g[d + 3];

    const float* f = freqs + (long)s * 256 + (d / 2) * 4;
    float o0 = f[0] * x0 + f[1] * x1;
    float o1 = f[2] * x0 + f[3] * x1;
    float o2 = f[4] * x2 + f[5] * x3;
    float o3 = f[6] * x2 + f[7] * x3;

    bf16 h0, l0, h1, l1, h2, l2, h3, l3;
    bsplit(o0, h0, l0); bsplit(o1, h1, l1);
    bsplit(o2, h2, l2); bsplit(o3, h3, l3);
    long oi = (long)r * DHEAD + lane * 4;
    *(uint2*)(oh + oi) = make_uint2(pack2(h0, h1), pack2(h2, h3));
    *(uint2*)(ol + oi) = make_uint2(pack2(l0, l1), pack2(l2, l3));
}

// ---------------------------------------------------------------------------
// Row softmax over 2304 elements
// ---------------------------------------------------------------------------
__global__ __launch_bounds__(256) void softmax_kernel(float* __restrict__ S)
{
    long row = blockIdx.x;
    float* p = S + row * 2304;
    int tid = threadIdx.x;

    float v[9];
    float mx = -INFINITY;
    #pragma unroll
    for (int i = 0; i < 9; i++) {
        v[i] = p[tid + i * 256];
        mx = fmaxf(mx, v[i]);
    }

    __shared__ float red[8];
    #pragma unroll
    for (int o = 16; o; o >>= 1) mx = fmaxf(mx, __shfl_xor_sync(0xffffffffu, mx, o));
    if ((tid & 31) == 0) red[tid >> 5] = mx;
    __syncthreads();
    float m = red[0];
    #pragma unroll
    for (int i = 1; i < 8; i++) m = fmaxf(m, red[i]);
    __syncthreads();

    float sum = 0.0f;
    #pragma unroll
    for (int i = 0; i < 9; i++) {
        v[i] = __expf(v[i] - m);
        sum += v[i];
    }
    #pragma unroll
    for (int o = 16; o; o >>= 1) sum += __shfl_xor_sync(0xffffffffu, sum, o);
    if ((tid & 31) == 0) red[tid >> 5] = sum;
    __syncthreads();
    float tot = 0.0f;
    #pragma unroll
    for (int i = 0; i < 8; i++) tot += red[i];
    float inv = 1.0f / tot;

    #pragma unroll
    for (int i = 0; i < 9; i++) p[tid + i * 256] = v[i] * inv;
}

// ---------------------------------------------------------------------------
extern "C" void kernel_launch(void* const* d_in, const int* in_sizes, int n_in,
                              void* d_out, int out_size)
{
    const float* hid   = (const float*)d_in[0];
    const float* enc   = (const float*)d_in[1];
    const float* freqs = (const float*)d_in[2];
    const float* W[8]  = { (const float*)d_in[3],  (const float*)d_in[4],
                           (const float*)d_in[5],  (const float*)d_in[6],
                           (const float*)d_in[7],  (const float*)d_in[8],
                           (const float*)d_in[13], (const float*)d_in[15] };
    const float* gq  = (const float*)d_in[9];
    const float* gk  = (const float*)d_in[10];
    const float* gaq = (const float*)d_in[11];
    const float* gak = (const float*)d_in[12];
    const float* bo  = (const float*)d_in[14];
    const float* bao = (const float*)d_in[16];
    float* out = (float*)d_out;

    float *q, *k, *v, *attn, *sc;
    bf16 *xh, *xl, *qh, *ql, *kh, *kl, *vth, *vtl, *ath, *atl, *wth, *wtl;
    cudaGetSymbolAddress((void**)&q,    g_q);
    cudaGetSymbolAddress((void**)&k,    g_k);
    cudaGetSymbolAddress((void**)&v,    g_v);
    cudaGetSymbolAddress((void**)&attn, g_attn);
    cudaGetSymbolAddress((void**)&sc,   g_s);
    cudaGetSymbolAddress((void**)&xh,   g_xh);
    cudaGetSymbolAddress((void**)&xl,   g_xl);
    cudaGetSymbolAddress((void**)&qh,   g_qh);
    cudaGetSymbolAddress((void**)&ql,   g_ql);
    cudaGetSymbolAddress((void**)&kh,   g_kh);
    cudaGetSymbolAddress((void**)&kl,   g_kl);
    cudaGetSymbolAddress((void**)&vth,  g_vth);
    cudaGetSymbolAddress((void**)&vtl,  g_vtl);
    cudaGetSymbolAddress((void**)&ath,  g_ath);
    cudaGetSymbolAddress((void**)&atl,  g_atl);
    cudaGetSymbolAddress((void**)&wth,  g_wth);
    cudaGetSymbolAddress((void**)&wtl,  g_wtl);

    cudaFuncSetAttribute(tgemm<true, false>, cudaFuncAttributeMaxDynamicSharedMemorySize, SMEMB_TOTAL);
    cudaFuncSetAttribute(tgemm<true, true>,  cudaFuncAttributeMaxDynamicSharedMemorySize, SMEMB_TOTAL);
    cudaFuncSetAttribute(tgemm<false,false>, cudaFuncAttributeMaxDynamicSharedMemorySize, SMEMB_TOTAL);

    dim3 blk(256);
    const long WSZ = (long)DMODEL * DMODEL;

    // split inputs into concatenated [enc;hid] hi/lo
    split_kernel<<<(SEQ_TXT * DMODEL / 4 + 255) / 256, 256>>>(enc, xh, xl, SEQ_TXT * DMODEL / 4);
    split_kernel<<<(SEQ_IMG * DMODEL / 4 + 255) / 256, 256>>>(
        hid, xh + (long)SEQ_TXT * DMODEL, xl + (long)SEQ_TXT * DMODEL, SEQ_IMG * DMODEL / 4);

    // transpose + split weights: wth[i][n*K+k] = hi(W[i][k][n])
    for (int i = 0; i < 8; i++)
        transpose_split_kernel<<<dim3(96, 96), dim3(32, 8)>>>(
            W[i], wth + i * WSZ, wtl + i * WSZ, DMODEL, DMODEL);

    // QKV projections. W[]: 0=Wq 1=Wk 2=Wv 3=Waq 4=Wak 5=Wav 6=Wo 7=Wao
    float* dst[3] = { q, k, v };
    for (int i = 0; i < 3; i++) {
        tgemm<true, false><<<dim3(24, 2, 1), blk, SMEMB_TOTAL>>>(
            nullptr, xh, xl, DMODEL, 0,
            wth + (3 + i) * WSZ, wtl + (3 + i) * WSZ, DMODEL, 0,
            dst[i], DMODEL, 0, DMODEL, nullptr, 1.0f);
        tgemm<true, false><<<dim3(24, 16, 1), blk, SMEMB_TOTAL>>>(
            nullptr, xh + (long)SEQ_TXT * DMODEL, xl + (long)SEQ_TXT * DMODEL, DMODEL, 0,
            wth + i * WSZ, wtl + i * WSZ, DMODEL, 0,
            dst[i] + (long)SEQ_TXT * DMODEL, DMODEL, 0, DMODEL, nullptr, 1.0f);
    }

    // RMSNorm + RoPE + split
    norm_rope_split_kernel<<<SEQ_TOT * NHEADS / 4, 128>>>(q, qh, ql, gq, gaq, freqs);
    norm_rope_split_kernel<<<SEQ_TOT * NHEADS / 4, 128>>>(k, kh, kl, gk, gak, freqs);

    // transpose + split V
    transpose_split_kernel<<<dim3(96, 72), dim3(32, 8)>>>(v, vth, vtl, SEQ_TOT, DMODEL);

    // Scores: S_h = scale * Q_h @ K_h^T
    const float scale = 0.088388347648318447f;
    tgemm<true, false><<<dim3(18, 18, 24), blk, SMEMB_TOTAL>>>(
        nullptr, qh, ql, DMODEL, 128,
        kh, kl, DMODEL, 128,
        sc, 2304, SS, DHEAD, nullptr, scale);

    // Softmax
    softmax_kernel<<<NHEADS * SEQ_TOT, 256>>>(sc);

    // PV: attn_h = P_h @ V_h  (A = probs fp32, split on load; B = vt pre-split)
    tgemm<false, false><<<dim3(1, 18, 24), blk, SMEMB_TOTAL>>>(
        sc, nullptr, nullptr, 2304, SS,
        vth, vtl, SEQ_TOT, (long)DHEAD * SEQ_TOT,
        attn, DMODEL, 128, SEQ_TOT, nullptr, 1.0f);

    // split attn for output projections
    split_kernel<<<(SEQ_TOT * DMODEL / 4 + 255) / 256, 256>>>(attn, ath, atl, SEQ_TOT * DMODEL / 4);

    // Output projections (img first, then txt)
    tgemm<true, true><<<dim3(24, 16, 1), blk, SMEMB_TOTAL>>>(
        nullptr, ath + (long)SEQ_TXT * DMODEL, atl + (long)SEQ_TXT * DMODEL, DMODEL, 0,
        wth + 6 * WSZ, wtl + 6 * WSZ, DMODEL, 0,
        out, DMODEL, 0, DMODEL, bo, 1.0f);
    tgemm<true, true><<<dim3(24, 2, 1), blk, SMEMB_TOTAL>>>(
        nullptr, ath, atl, DMODEL, 0,
        wth + 7 * WSZ, wtl + 7 * WSZ, DMODEL, 0,
        out + (long)SEQ_IMG * DMODEL, DMODEL, 0, DMODEL, bao, 1.0f);
}

// round 7
// speedup vs baseline: 3.1592x; 1.0727x over previous
#include <cuda_runtime.h>
#include <cuda_bf16.h>
#include <math.h>
#include <stdint.h>

// Problem constants
#define SEQ_TXT 256
#define SEQ_IMG 2048
#define SEQ_TOT 2304
#define DMODEL  3072
#define NHEADS  24
#define DHEAD   128

typedef __nv_bfloat16 bf16;

// fp32 scratch
__device__ float g_q[SEQ_TOT * DMODEL];
__device__ float g_k[SEQ_TOT * DMODEL];
__device__ float g_v[SEQ_TOT * DMODEL];

// bf16 hi/lo pre-split operands
__device__ bf16 g_xh[SEQ_TOT * DMODEL],  g_xl[SEQ_TOT * DMODEL];    // [enc;hid]
__device__ bf16 g_qh[SEQ_TOT * DMODEL],  g_ql[SEQ_TOT * DMODEL];
__device__ bf16 g_kh[SEQ_TOT * DMODEL],  g_kl[SEQ_TOT * DMODEL];
__device__ bf16 g_vth[DMODEL * SEQ_TOT], g_vtl[DMODEL * SEQ_TOT];
__device__ bf16 g_ath[SEQ_TOT * DMODEL], g_atl[SEQ_TOT * DMODEL];
__device__ bf16 g_wth[8][DMODEL * (long)DMODEL];
__device__ bf16 g_wtl[8][DMODEL * (long)DMODEL];

__device__ __forceinline__ void bsplit(float x, bf16& h, bf16& l) {
    h = __float2bfloat16_rn(x);
    l = __float2bfloat16_rn(x - __bfloat162float(h));
}
__device__ __forceinline__ uint32_t pack2(bf16 a, bf16 b) {
    __nv_bfloat162 t = __halves2bfloat162(a, b);
    return *(uint32_t*)&t;
}

#define MMA_BF16(CV, AV, BV) \
    asm volatile( \
        "mma.sync.aligned.m16n8k16.row.col.f32.bf16.bf16.f32 " \
        "{%0,%1,%2,%3}, {%4,%5,%6,%7}, {%8,%9}, {%0,%1,%2,%3};" \
        : "+f"((CV)[0]), "+f"((CV)[1]), "+f"((CV)[2]), "+f"((CV)[3]) \
        : "r"((AV)[0]), "r"((AV)[1]), "r"((AV)[2]), "r"((AV)[3]), \
          "r"((BV)[0]), "r"((BV)[1]))

// ---------------------------------------------------------------------------
// bf16x3 tensor-core GEMM (pre-split operands): C = alpha * A @ B^T (+bias)
// ---------------------------------------------------------------------------
#define WSTRIDE 20
#define TILE_WORDS (128 * WSTRIDE)
#define SMEMB_TOTAL (8 * TILE_WORDS * 4)   // 81920 bytes

template<bool BIAS>
__global__ __launch_bounds__(256) void tgemm(
    const bf16* __restrict__ Ahi, const bf16* __restrict__ Alo, int lda,
    const bf16* __restrict__ Bhi, const bf16* __restrict__ Blo, int ldb,
    float* __restrict__ C, int ldc,
    int K, const float* __restrict__ bias, float alpha)
{
    extern __shared__ uint32_t sm[];
    uint32_t* smAhi = sm;
    uint32_t* smAlo = sm + 2 * TILE_WORDS;
    uint32_t* smBhi = sm + 4 * TILE_WORDS;
    uint32_t* smBlo = sm + 6 * TILE_WORDS;

    const int row0 = blockIdx.y * 128;
    const int col0 = blockIdx.x * 128;

    const int tid  = threadIdx.x;
    const int lane = tid & 31;
    const int wid  = tid >> 5;
    const int m_off = (wid & 3) * 32;
    const int n_off = (wid >> 2) * 64;
    const int lr = lane >> 2;
    const int lc = lane & 3;

    const int pr = tid >> 2;
    const int pw = (tid & 3) * 4;

    uint4 rah[2], ral[2], rbh[2], rbl[2];

    auto gload = [&](int k0) {
        #pragma unroll
        for (int p = 0; p < 2; p++) {
            long ro = (long)(row0 + pr + p * 64) * lda + k0 + pw * 2;
            rah[p] = *(const uint4*)(Ahi + ro);
            ral[p] = *(const uint4*)(Alo + ro);
            long co = (long)(col0 + pr + p * 64) * ldb + k0 + pw * 2;
            rbh[p] = *(const uint4*)(Bhi + co);
            rbl[p] = *(const uint4*)(Blo + co);
        }
    };
    auto stage = [&](int buf) {
        #pragma unroll
        for (int p = 0; p < 2; p++) {
            int off = (pr + p * 64) * WSTRIDE + pw;
            *(uint4*)(smAhi + buf * TILE_WORDS + off) = rah[p];
            *(uint4*)(smAlo + buf * TILE_WORDS + off) = ral[p];
            *(uint4*)(smBhi + buf * TILE_WORDS + off) = rbh[p];
            *(uint4*)(smBlo + buf * TILE_WORDS + off) = rbl[p];
        }
    };

    gload(0);
    stage(0);
    __syncthreads();

    float acc[2][8][4];
    #pragma unroll
    for (int mt = 0; mt < 2; mt++)
        #pragma unroll
        for (int nt = 0; nt < 8; nt++)
            #pragma unroll
            for (int i = 0; i < 4; i++) acc[mt][nt][i] = 0.0f;

    const int nIter = K >> 5;
    for (int it = 0; it < nIter; ++it) {
        const int cur = it & 1;
        if (it + 1 < nIter) gload((it + 1) * 32);

        const uint32_t* cAh = smAhi + cur * TILE_WORDS;
        const uint32_t* cAl = smAlo + cur * TILE_WORDS;
        const uint32_t* cBh = smBhi + cur * TILE_WORDS;
        const uint32_t* cBl = smBlo + cur * TILE_WORDS;

        #pragma unroll
        for (int ks = 0; ks < 2; ks++) {
            uint32_t ah[2][4], al[2][4], bh[8][2], bl[8][2];
            #pragma unroll
            for (int mt = 0; mt < 2; mt++) {
                int r = m_off + mt * 16 + lr;
                int o0 = r * WSTRIDE + ks * 8 + lc;
                int o1 = (r + 8) * WSTRIDE + ks * 8 + lc;
                ah[mt][0] = cAh[o0];     ah[mt][1] = cAh[o1];
                ah[mt][2] = cAh[o0 + 4]; ah[mt][3] = cAh[o1 + 4];
                al[mt][0] = cAl[o0];     al[mt][1] = cAl[o1];
                al[mt][2] = cAl[o0 + 4]; al[mt][3] = cAl[o1 + 4];
            }
            #pragma unroll
            for (int nt = 0; nt < 8; nt++) {
                int o = (n_off + nt * 8 + lr) * WSTRIDE + ks * 8 + lc;
                bh[nt][0] = cBh[o]; bh[nt][1] = cBh[o + 4];
                bl[nt][0] = cBl[o]; bl[nt][1] = cBl[o + 4];
            }
            #pragma unroll
            for (int mt = 0; mt < 2; mt++)
                #pragma unroll
                for (int nt = 0; nt < 8; nt++) {
                    MMA_BF16(acc[mt][nt], ah[mt], bh[nt]);
                    MMA_BF16(acc[mt][nt], ah[mt], bl[nt]);
                    MMA_BF16(acc[mt][nt], al[mt], bh[nt]);
                }
        }

        if (it + 1 < nIter) stage(cur ^ 1);
        __syncthreads();
    }

    #pragma unroll
    for (int mt = 0; mt < 2; mt++) {
        #pragma unroll
        for (int nt = 0; nt < 8; nt++) {
            int r0 = row0 + m_off + mt * 16 + lr;
            int cc = col0 + n_off + nt * 8 + lc * 2;
            float2 v0, v1;
            v0.x = acc[mt][nt][0] * alpha;
            v0.y = acc[mt][nt][1] * alpha;
            v1.x = acc[mt][nt][2] * alpha;
            v1.y = acc[mt][nt][3] * alpha;
            if (BIAS) {
                v0.x += bias[cc]; v0.y += bias[cc + 1];
                v1.x += bias[cc]; v1.y += bias[cc + 1];
            }
            *(float2*)(C + (long)r0 * ldc + cc)       = v0;
            *(float2*)(C + (long)(r0 + 8) * ldc + cc) = v1;
        }
    }
}

// ---------------------------------------------------------------------------
// Flash attention: per (q-block 128, head) CTA; online softmax over 18 KV tiles.
// All operands bf16 hi/lo; S and PV via bf16x3 mma. Writes attn split hi/lo.
// smem tiles: 128 rows x 64 words, row stride 68 words.
// ---------------------------------------------------------------------------
#define FTW 8704                       // flash tile words (128*68)
#define FLASH_SMEM (6 * FTW * 4)       // 208896 bytes

__global__ __launch_bounds__(256, 1) void flash_kernel(
    const bf16* __restrict__ Qh, const bf16* __restrict__ Ql,
    const bf16* __restrict__ Kh, const bf16* __restrict__ Kl,
    const bf16* __restrict__ Vh, const bf16* __restrict__ Vl,
    bf16* __restrict__ Oh, bf16* __restrict__ Ol)
{
    extern __shared__ uint32_t sm[];
    __shared__ float red[4][8][4][2];

    const int h  = blockIdx.y;
    const int q0 = blockIdx.x * 128;
    const int tid = threadIdx.x;
    const int lane = tid & 31, wid = tid >> 5;
    const int m_off = (wid & 3) * 32, n_off = (wid >> 2) * 64;
    const int lr = lane >> 2, lc = lane & 3;
    const int mg = wid & 3, gg = wid >> 2;

    uint32_t* sQh = sm;
    uint32_t* sQl = sm + FTW;
    uint32_t* sPh = sm + 2 * FTW;   // K tile, then overwritten by P
    uint32_t* sPl = sm + 3 * FTW;
    uint32_t* sVh = sm + 4 * FTW;
    uint32_t* sVl = sm + 5 * FTW;

    auto load_tile = [&](uint32_t* dh, uint32_t* dl,
                         const bf16* gh, const bf16* gl,
                         int rs0, int cs0, int pitch) {
        #pragma unroll
        for (int i = 0; i < 8; i++) {
            int idx = tid + 256 * i;
            int r = idx >> 4, u = idx & 15;
            long go = (long)(rs0 + r) * pitch + cs0 + u * 8;
            *(uint4*)(dh + r * 68 + u * 4) = *(const uint4*)(gh + go);
            *(uint4*)(dl + r * 68 + u * 4) = *(const uint4*)(gl + go);
        }
    };

    load_tile(sQh, sQl, Qh, Ql, q0, h * DHEAD, DMODEL);

    float m_i[4], l_i[4], oacc[2][8][4];
    #pragma unroll
    for (int s = 0; s < 4; s++) { m_i[s] = -INFINITY; l_i[s] = 0.0f; }
    #pragma unroll
    for (int mt = 0; mt < 2; mt++)
        #pragma unroll
        for (int nt = 0; nt < 8; nt++)
            #pragma unroll
            for (int c = 0; c < 4; c++) oacc[mt][nt][c] = 0.0f;

    for (int kv = 0; kv < SEQ_TOT / 128; kv++) {
        const int kv0 = kv * 128;
        __syncthreads();   // prev PV reads of sP/sV done
        load_tile(sPh, sPl, Kh, Kl, kv0, h * DHEAD, DMODEL);
        load_tile(sVh, sVl, Vh, Vl, h * DHEAD, kv0, SEQ_TOT);
        __syncthreads();

        // ---- S = Q @ K^T (scale pre-folded into Q) ----
        float sacc[2][8][4];
        #pragma unroll
        for (int mt = 0; mt < 2; mt++)
            #pragma unroll
            for (int nt = 0; nt < 8; nt++)
                #pragma unroll
                for (int c = 0; c < 4; c++) sacc[mt][nt][c] = 0.0f;

        #pragma unroll
        for (int ks = 0; ks < 8; ks++) {
            uint32_t ah[2][4], al[2][4], bh[8][2], bl[8][2];
            #pragma unroll
            for (int mt = 0; mt < 2; mt++) {
                int o0 = (m_off + mt * 16 + lr) * 68 + ks * 8 + lc;
                int o1 = o0 + 8 * 68;
                ah[mt][0] = sQh[o0];     ah[mt][1] = sQh[o1];
                ah[mt][2] = sQh[o0 + 4]; ah[mt][3] = sQh[o1 + 4];
                al[mt][0] = sQl[o0];     al[mt][1] = sQl[o1];
                al[mt][2] = sQl[o0 + 4]; al[mt][3] = sQl[o1 + 4];
            }
            #pragma unroll
            for (int nt = 0; nt < 8; nt++) {
                int o = (n_off + nt * 8 + lr) * 68 + ks * 8 + lc;
                bh[nt][0] = sPh[o]; bh[nt][1] = sPh[o + 4];
                bl[nt][0] = sPl[o]; bl[nt][1] = sPl[o + 4];
            }
            #pragma unroll
            for (int mt = 0; mt < 2; mt++)
                #pragma unroll
                for (int nt = 0; nt < 8; nt++) {
                    MMA_BF16(sacc[mt][nt], ah[mt], bh[nt]);
                    MMA_BF16(sacc[mt][nt], ah[mt], bl[nt]);
                    MMA_BF16(sacc[mt][nt], al[mt], bh[nt]);
                }
        }

        // ---- online softmax ----
        float mx4[4];
        #pragma unroll
        for (int s = 0; s < 4; s++) {
            int mt = s >> 1, c0 = (s & 1) * 2;
            float mx = sacc[mt][0][c0];
            #pragma unroll
            for (int nt = 0; nt < 8; nt++) {
                mx = fmaxf(mx, sacc[mt][nt][c0]);
                mx = fmaxf(mx, sacc[mt][nt][c0 + 1]);
            }
            mx = fmaxf(mx, __shfl_xor_sync(0xffffffffu, mx, 1));
            mx = fmaxf(mx, __shfl_xor_sync(0xffffffffu, mx, 2));
            mx4[s] = mx;
            if (lc == 0) red[mg][lr][s][gg] = mx;
        }
        __syncthreads();

        float a4[4], mnew[4];
        #pragma unroll
        for (int s = 0; s < 4; s++) {
            mnew[s] = fmaxf(m_i[s], fmaxf(mx4[s], red[mg][lr][s][gg ^ 1]));
            a4[s] = __expf(m_i[s] - mnew[s]);
            m_i[s] = mnew[s];
            l_i[s] *= a4[s];
        }

        float rs4[4] = {0.f, 0.f, 0.f, 0.f};
        #pragma unroll
        for (int mt = 0; mt < 2; mt++)
            #pragma unroll
            for (int nt = 0; nt < 8; nt++)
                #pragma unroll
                for (int c = 0; c < 4; c++) {
                    int s = mt * 2 + (c >> 1);
                    float e = __expf(sacc[mt][nt][c] - mnew[s]);
                    sacc[mt][nt][c] = e;
                    rs4[s] += e;
                }
        #pragma unroll
        for (int s = 0; s < 4; s++) {
            rs4[s] += __shfl_xor_sync(0xffffffffu, rs4[s], 1);
            rs4[s] += __shfl_xor_sync(0xffffffffu, rs4[s], 2);
        }
        #pragma unroll
        for (int mt = 0; mt < 2; mt++)
            #pragma unroll
            for (int nt = 0; nt < 8; nt++) {
                oacc[mt][nt][0] *= a4[mt * 2];
                oacc[mt][nt][1] *= a4[mt * 2];
                oacc[mt][nt][2] *= a4[mt * 2 + 1];
                oacc[mt][nt][3] *= a4[mt * 2 + 1];
            }
        __syncthreads();   // all max reads complete before reusing red / sP

        #pragma unroll
        for (int s = 0; s < 4; s++)
            if (lc == 0) red[mg][lr][s][gg] = rs4[s];

        // write P (bf16 hi/lo) over the K tile
        #pragma unroll
        for (int mt = 0; mt < 2; mt++)
            #pragma unroll
            for (int nt = 0; nt < 8; nt++) {
                int w = (n_off >> 1) + nt * 4 + lc;
                int o = (m_off + mt * 16 + lr) * 68 + w;
                bf16 h0, l0, h1, l1;
                bsplit(sacc[mt][nt][0], h0, l0);
                bsplit(sacc[mt][nt][1], h1, l1);
                sPh[o] = pack2(h0, h1); sPl[o] = pack2(l0, l1);
                bsplit(sacc[mt][nt][2], h0, l0);
                bsplit(sacc[mt][nt][3], h1, l1);
                sPh[o + 8 * 68] = pack2(h0, h1); sPl[o + 8 * 68] = pack2(l0, l1);
            }
        __syncthreads();

        #pragma unroll
        for (int s = 0; s < 4; s++)
            l_i[s] += rs4[s] + red[mg][lr][s][gg ^ 1];

        // ---- O += P @ V ----
        #pragma unroll
        for (int ks = 0; ks < 8; ks++) {
            uint32_t ah[2][4], al[2][4], bh[8][2], bl[8][2];
            #pragma unroll
            for (int mt = 0; mt < 2; mt++) {
                int o0 = (m_off + mt * 16 + lr) * 68 + ks * 8 + lc;
                int o1 = o0 + 8 * 68;
                ah[mt][0] = sPh[o0];     ah[mt][1] = sPh[o1];
                ah[mt][2] = sPh[o0 + 4]; ah[mt][3] = sPh[o1 + 4];
                al[mt][0] = sPl[o0];     al[mt][1] = sPl[o1];
                al[mt][2] = sPl[o0 + 4]; al[mt][3] = sPl[o1 + 4];
            }
            #pragma unroll
            for (int nt = 0; nt < 8; nt++) {
                int o = (n_off + nt * 8 + lr) * 68 + ks * 8 + lc;
                bh[nt][0] = sVh[o]; bh[nt][1] = sVh[o + 4];
                bl[nt][0] = sVl[o]; bl[nt][1] = sVl[o + 4];
            }
            #pragma unroll
            for (int mt = 0; mt < 2; mt++)
                #pragma unroll
                for (int nt = 0; nt < 8; nt++) {
                    MMA_BF16(oacc[mt][nt], ah[mt], bh[nt]);
                    MMA_BF16(oacc[mt][nt], ah[mt], bl[nt]);
                    MMA_BF16(oacc[mt][nt], al[mt], bh[nt]);
                }
        }
    }

    // ---- epilogue: normalize and write attn split hi/lo ----
    #pragma unroll
    for (int mt = 0; mt < 2; mt++) {
        float i0 = 1.0f / l_i[mt * 2];
        float i1 = 1.0f / l_i[mt * 2 + 1];
        #pragma unroll
        for (int nt = 0; nt < 8; nt++) {
            int col = h * DHEAD + n_off + nt * 8 + lc * 2;
            long r0 = q0 + m_off + mt * 16 + lr;
            bf16 h0, l0, h1, l1;
            bsplit(oacc[mt][nt][0] * i0, h0, l0);
            bsplit(oacc[mt][nt][1] * i0, h1, l1);
            *(uint32_t*)(Oh + r0 * DMODEL + col) = pack2(h0, h1);
            *(uint32_t*)(Ol + r0 * DMODEL + col) = pack2(l0, l1);
            bsplit(oacc[mt][nt][2] * i1, h0, l0);
            bsplit(oacc[mt][nt][3] * i1, h1, l1);
            *(uint32_t*)(Oh + (r0 + 8) * DMODEL + col) = pack2(h0, h1);
            *(uint32_t*)(Ol + (r0 + 8) * DMODEL + col) = pack2(l0, l1);
        }
    }
}

// ---------------------------------------------------------------------------
// elementwise split: fp32 -> bf16 hi/lo
// ---------------------------------------------------------------------------
__global__ __launch_bounds__(256) void split_kernel(
    const float* __restrict__ in, bf16* __restrict__ hi, bf16* __restrict__ lo, int n4)
{
    int idx = blockIdx.x * 256 + threadIdx.x;
    if (idx >= n4) return;
    float4 v = ((const float4*)in)[idx];
    bf16 h0, l0, h1, l1, h2, l2, h3, l3;
    bsplit(v.x, h0, l0); bsplit(v.y, h1, l1);
    bsplit(v.z, h2, l2); bsplit(v.w, h3, l3);
    ((uint2*)hi)[idx] = make_uint2(pack2(h0, h1), pack2(h2, h3));
    ((uint2*)lo)[idx] = make_uint2(pack2(l0, l1), pack2(l2, l3));
}

// ---------------------------------------------------------------------------
// 32x32 tiled transpose + split
// ---------------------------------------------------------------------------
__global__ __launch_bounds__(256) void transpose_split_kernel(
    const float* __restrict__ in, bf16* __restrict__ hi, bf16* __restrict__ lo,
    int rows, int cols)
{
    __shared__ float t[32][33];
    int bx = blockIdx.x * 32;
    int by = blockIdx.y * 32;
    int x = bx + threadIdx.x;
    #pragma unroll
    for (int j = 0; j < 32; j += 8)
        t[threadIdx.y + j][threadIdx.x] = in[(long)(by + threadIdx.y + j) * cols + x];
    __syncthreads();
    int y = by + threadIdx.x;
    #pragma unroll
    for (int j = 0; j < 32; j += 8) {
        float val = t[threadIdx.x][threadIdx.y + j];
        bf16 h, l;
        bsplit(val, h, l);
        long o = (long)(bx + threadIdx.y + j) * rows + y;
        hi[o] = h; lo[o] = l;
    }
}

// ---------------------------------------------------------------------------
// RMSNorm + RoPE + optional scale, output split to bf16 hi/lo
// ---------------------------------------------------------------------------
__global__ __launch_bounds__(128) void norm_rope_split_kernel(
    const float* __restrict__ x,
    bf16* __restrict__ oh, bf16* __restrict__ ol,
    const float* __restrict__ g_im,
    const float* __restrict__ g_tx,
    const float* __restrict__ freqs, float sc)
{
    int r = blockIdx.x * 4 + (threadIdx.x >> 5);
    int lane = threadIdx.x & 31;
    int s = r / NHEADS;

    const float* p = x + (long)r * DHEAD + lane * 4;
    float4 v = *(const float4*)p;

    float ss = v.x * v.x + v.y * v.y + v.z * v.z + v.w * v.w;
    #pragma unroll
    for (int o = 16; o; o >>= 1) ss += __shfl_xor_sync(0xffffffffu, ss, o);
    float rn = rsqrtf(ss * (1.0f / 128.0f) + 1e-5f);

    const float* g = (s < SEQ_TXT) ? g_tx : g_im;
    int d = lane * 4;
    float x0 = v.x * rn * g[d + 0];
    float x1 = v.y * rn * g[d + 1];
    float x2 = v.z * rn * g[d + 2];
    float x3 = v.w * rn * g[d + 3];

    const float* f = freqs + (long)s * 256 + (d / 2) * 4;
    float o0 = (f[0] * x0 + f[1] * x1) * sc;
    float o1 = (f[2] * x0 + f[3] * x1) * sc;
    float o2 = (f[4] * x2 + f[5] * x3) * sc;
    float o3 = (f[6] * x2 + f[7] * x3) * sc;

    bf16 h0, l0, h1, l1, h2, l2, h3, l3;
    bsplit(o0, h0, l0); bsplit(o1, h1, l1);
    bsplit(o2, h2, l2); bsplit(o3, h3, l3);
    long oi = (long)r * DHEAD + lane * 4;
    *(uint2*)(oh + oi) = make_uint2(pack2(h0, h1), pack2(h2, h3));
    *(uint2*)(ol + oi) = make_uint2(pack2(l0, l1), pack2(l2, l3));
}

// ---------------------------------------------------------------------------
extern "C" void kernel_launch(void* const* d_in, const int* in_sizes, int n_in,
                              void* d_out, int out_size)
{
    const float* hid   = (const float*)d_in[0];
    const float* enc   = (const float*)d_in[1];
    const float* freqs = (const float*)d_in[2];
    const float* W[8]  = { (const float*)d_in[3],  (const float*)d_in[4],
                           (const float*)d_in[5],  (const float*)d_in[6],
                           (const float*)d_in[7],  (const float*)d_in[8],
                           (const float*)d_in[13], (const float*)d_in[15] };
    const float* gq  = (const float*)d_in[9];
    const float* gk  = (const float*)d_in[10];
    const float* gaq = (const float*)d_in[11];
    const float* gak = (const float*)d_in[12];
    const float* bo  = (const float*)d_in[14];
    const float* bao = (const float*)d_in[16];
    float* out = (float*)d_out;

    float *q, *k, *v;
    bf16 *xh, *xl, *qh, *ql, *kh, *kl, *vth, *vtl, *ath, *atl, *wth, *wtl;
    cudaGetSymbolAddress((void**)&q,   g_q);
    cudaGetSymbolAddress((void**)&k,   g_k);
    cudaGetSymbolAddress((void**)&v,   g_v);
    cudaGetSymbolAddress((void**)&xh,  g_xh);
    cudaGetSymbolAddress((void**)&xl,  g_xl);
    cudaGetSymbolAddress((void**)&qh,  g_qh);
    cudaGetSymbolAddress((void**)&ql,  g_ql);
    cudaGetSymbolAddress((void**)&kh,  g_kh);
    cudaGetSymbolAddress((void**)&kl,  g_kl);
    cudaGetSymbolAddress((void**)&vth, g_vth);
    cudaGetSymbolAddress((void**)&vtl, g_vtl);
    cudaGetSymbolAddress((void**)&ath, g_ath);
    cudaGetSymbolAddress((void**)&atl, g_atl);
    cudaGetSymbolAddress((void**)&wth, g_wth);
    cudaGetSymbolAddress((void**)&wtl, g_wtl);

    cudaFuncSetAttribute(tgemm<false>, cudaFuncAttributeMaxDynamicSharedMemorySize, SMEMB_TOTAL);
    cudaFuncSetAttribute(tgemm<true>,  cudaFuncAttributeMaxDynamicSharedMemorySize, SMEMB_TOTAL);
    cudaFuncSetAttribute(flash_kernel, cudaFuncAttributeMaxDynamicSharedMemorySize, FLASH_SMEM);

    dim3 blk(256);
    const long WSZ = (long)DMODEL * DMODEL;

    // split inputs into concatenated [enc;hid] hi/lo
    split_kernel<<<(SEQ_TXT * DMODEL / 4 + 255) / 256, 256>>>(enc, xh, xl, SEQ_TXT * DMODEL / 4);
    split_kernel<<<(SEQ_IMG * DMODEL / 4 + 255) / 256, 256>>>(
        hid, xh + (long)SEQ_TXT * DMODEL, xl + (long)SEQ_TXT * DMODEL, SEQ_IMG * DMODEL / 4);

    // transpose + split weights
    for (int i = 0; i < 8; i++)
        transpose_split_kernel<<<dim3(96, 96), dim3(32, 8)>>>(
            W[i], wth + i * WSZ, wtl + i * WSZ, DMODEL, DMODEL);

    // QKV projections. W[]: 0=Wq 1=Wk 2=Wv 3=Waq 4=Wak 5=Wav 6=Wo 7=Wao
    float* dst[3] = { q, k, v };
    for (int i = 0; i < 3; i++) {
        tgemm<false><<<dim3(24, 2, 1), blk, SMEMB_TOTAL>>>(
            xh, xl, DMODEL,
            wth + (3 + i) * WSZ, wtl + (3 + i) * WSZ, DMODEL,
            dst[i], DMODEL, DMODEL, nullptr, 1.0f);
        tgemm<false><<<dim3(24, 16, 1), blk, SMEMB_TOTAL>>>(
            xh + (long)SEQ_TXT * DMODEL, xl + (long)SEQ_TXT * DMODEL, DMODEL,
            wth + i * WSZ, wtl + i * WSZ, DMODEL,
            dst[i] + (long)SEQ_TXT * DMODEL, DMODEL, DMODEL, nullptr, 1.0f);
    }

    // RMSNorm + RoPE + split (fold 1/sqrt(DHEAD) into q)
    const float scale = 0.088388347648318447f;
    norm_rope_split_kernel<<<SEQ_TOT * NHEADS / 4, 128>>>(q, qh, ql, gq, gaq, freqs, scale);
    norm_rope_split_kernel<<<SEQ_TOT * NHEADS / 4, 128>>>(k, kh, kl, gk, gak, freqs, 1.0f);

    // transpose + split V
    transpose_split_kernel<<<dim3(96, 72), dim3(32, 8)>>>(v, vth, vtl, SEQ_TOT, DMODEL);

    // fused attention -> ath/atl (bf16 hi/lo)
    flash_kernel<<<dim3(SEQ_TOT / 128, NHEADS), blk, FLASH_SMEM>>>(
        qh, ql, kh, kl, vth, vtl, ath, atl);

    // Output projections (img first, then txt)
    tgemm<true><<<dim3(24, 16, 1), blk, SMEMB_TOTAL>>>(
        ath + (long)SEQ_TXT * DMODEL, atl + (long)SEQ_TXT * DMODEL, DMODEL,
        wth + 6 * WSZ, wtl + 6 * WSZ, DMODEL,
        out, DMODEL, DMODEL, bo, 1.0f);
    tgemm<true><<<dim3(24, 2, 1), blk, SMEMB_TOTAL>>>(
        ath, atl, DMODEL,
        wth + 7 * WSZ, wtl + 7 * WSZ, DMODEL,
        out + (long)SEQ_IMG * DMODEL, DMODEL, DMODEL, bao, 1.0f);
}

// round 8
// speedup vs baseline: 4.0045x; 1.2676x over previous
#include <cuda_runtime.h>
#include <cuda_bf16.h>
#include <math.h>
#include <stdint.h>

// Problem constants
#define SEQ_TXT 256
#define SEQ_IMG 2048
#define SEQ_TOT 2304
#define DMODEL  3072
#define NHEADS  24
#define DHEAD   128
#define QKVP    (3 * DMODEL)   // 9216 qkv row pitch

typedef __nv_bfloat16 bf16;

// fp32 scratch: concatenated [q|k|v] per row
__device__ float g_qkv[SEQ_TOT * (long)QKVP];

// bf16 hi/lo pre-split operands
__device__ bf16 g_xh[SEQ_TOT * DMODEL],  g_xl[SEQ_TOT * DMODEL];
__device__ bf16 g_qh[SEQ_TOT * DMODEL],  g_ql[SEQ_TOT * DMODEL];
__device__ bf16 g_kh[SEQ_TOT * DMODEL],  g_kl[SEQ_TOT * DMODEL];
__device__ bf16 g_vth[DMODEL * SEQ_TOT], g_vtl[DMODEL * SEQ_TOT];
__device__ bf16 g_ath[SEQ_TOT * DMODEL], g_atl[SEQ_TOT * DMODEL];
__device__ bf16 g_wth[8][DMODEL * (long)DMODEL];
__device__ bf16 g_wtl[8][DMODEL * (long)DMODEL];

__device__ __forceinline__ void bsplit(float x, bf16& h, bf16& l) {
    h = __float2bfloat16_rn(x);
    l = __float2bfloat16_rn(x - __bfloat162float(h));
}
__device__ __forceinline__ uint32_t pack2(bf16 a, bf16 b) {
    __nv_bfloat162 t = __halves2bfloat162(a, b);
    return *(uint32_t*)&t;
}
__device__ __forceinline__ uint32_t cvta_s(const void* p) {
    return (uint32_t)__cvta_generic_to_shared(p);
}

#define MMA_BF16(CV, AV, BV) \
    asm volatile( \
        "mma.sync.aligned.m16n8k16.row.col.f32.bf16.bf16.f32 " \
        "{%0,%1,%2,%3}, {%4,%5,%6,%7}, {%8,%9}, {%0,%1,%2,%3};" \
        : "+f"((CV)[0]), "+f"((CV)[1]), "+f"((CV)[2]), "+f"((CV)[3]) \
        : "r"((AV)[0]), "r"((AV)[1]), "r"((AV)[2]), "r"((AV)[3]), \
          "r"((BV)[0]), "r"((BV)[1]))

#define LDSM_X4(R, ADDR) \
    asm volatile("ldmatrix.sync.aligned.m8n8.x4.shared.b16 {%0,%1,%2,%3}, [%4];" \
        : "=r"((R)[0]), "=r"((R)[1]), "=r"((R)[2]), "=r"((R)[3]) : "r"(ADDR))

// ---------------------------------------------------------------------------
// bf16x3 tensor-core GEMM (pre-split operands): C = alpha * A @ B^T (+bias)
// Tiles 128x128x32, 8 warps (32x64), double-buffered, ldmatrix fragments.
// ---------------------------------------------------------------------------
#define WSTRIDE 20
#define TILE_WORDS (128 * WSTRIDE)
#define TWB (TILE_WORDS * 4)
#define SMEMB_TOTAL (8 * TWB)   // 81920 bytes

template<bool BIAS>
__global__ __launch_bounds__(256) void tgemm(
    const bf16* __restrict__ Ahi, const bf16* __restrict__ Alo, int lda,
    const bf16* __restrict__ Bhi, const bf16* __restrict__ Blo, int ldb,
    float* __restrict__ C, int ldc,
    int K, const float* __restrict__ bias, float alpha)
{
    extern __shared__ uint32_t sm[];
    uint32_t* smAhi = sm;
    uint32_t* smAlo = sm + 2 * TILE_WORDS;
    uint32_t* smBhi = sm + 4 * TILE_WORDS;
    uint32_t* smBlo = sm + 6 * TILE_WORDS;

    const int row0 = blockIdx.y * 128;
    const int col0 = blockIdx.x * 128;

    const int tid  = threadIdx.x;
    const int lane = tid & 31;
    const int wid  = tid >> 5;
    const int m_off = (wid & 3) * 32;
    const int n_off = (wid >> 2) * 64;
    const int lr = lane >> 2;
    const int lc = lane & 3;

    // ldmatrix lane addressing (byte offsets into a tile)
    const uint32_t sbase = cvta_s(sm);
    const uint32_t aoff = ((m_off + (lane & 15)) * WSTRIDE + ((lane >> 4) & 1) * 4) * 4;
    const uint32_t boff = ((n_off + (lane & 7) + ((lane >> 4) & 1) * 8) * WSTRIDE
                           + ((lane >> 3) & 1) * 4) * 4;
    const uint32_t aHi = sbase + aoff,            aLo = sbase + 2 * TWB + aoff;
    const uint32_t bHi = sbase + 4 * TWB + boff,  bLo = sbase + 6 * TWB + boff;
    const uint32_t MT_OFF = 16 * WSTRIDE * 4;     // 16-row step in bytes

    const int pr = tid >> 2;
    const int pw = (tid & 3) * 4;

    uint4 rah[2], ral[2], rbh[2], rbl[2];

    auto gload = [&](int k0) {
        #pragma unroll
        for (int p = 0; p < 2; p++) {
            long ro = (long)(row0 + pr + p * 64) * lda + k0 + pw * 2;
            rah[p] = *(const uint4*)(Ahi + ro);
            ral[p] = *(const uint4*)(Alo + ro);
            long co = (long)(col0 + pr + p * 64) * ldb + k0 + pw * 2;
            rbh[p] = *(const uint4*)(Bhi + co);
            rbl[p] = *(const uint4*)(Blo + co);
        }
    };
    auto stage = [&](int buf) {
        #pragma unroll
        for (int p = 0; p < 2; p++) {
            int off = (pr + p * 64) * WSTRIDE + pw;
            *(uint4*)(smAhi + buf * TILE_WORDS + off) = rah[p];
            *(uint4*)(smAlo + buf * TILE_WORDS + off) = ral[p];
            *(uint4*)(smBhi + buf * TILE_WORDS + off) = rbh[p];
            *(uint4*)(smBlo + buf * TILE_WORDS + off) = rbl[p];
        }
    };

    gload(0);
    stage(0);
    __syncthreads();

    float acc[2][8][4];
    #pragma unroll
    for (int mt = 0; mt < 2; mt++)
        #pragma unroll
        for (int nt = 0; nt < 8; nt++)
            #pragma unroll
            for (int i = 0; i < 4; i++) acc[mt][nt][i] = 0.0f;

    const int nIter = K >> 5;
    for (int it = 0; it < nIter; ++it) {
        const int cur = it & 1;
        if (it + 1 < nIter) gload((it + 1) * 32);
        const uint32_t bufB = cur * TWB;

        #pragma unroll
        for (int ks = 0; ks < 2; ks++) {
            uint32_t ah[2][4], al[2][4], bh[4][4], bl[4][4];
            #pragma unroll
            for (int mt = 0; mt < 2; mt++) {
                LDSM_X4(ah[mt], aHi + bufB + mt * MT_OFF + ks * 32);
                LDSM_X4(al[mt], aLo + bufB + mt * MT_OFF + ks * 32);
            }
            #pragma unroll
            for (int p = 0; p < 4; p++) {
                LDSM_X4(bh[p], bHi + bufB + p * MT_OFF + ks * 32);
                LDSM_X4(bl[p], bLo + bufB + p * MT_OFF + ks * 32);
            }
            #pragma unroll
            for (int mt = 0; mt < 2; mt++)
                #pragma unroll
                for (int nt = 0; nt < 8; nt++) {
                    uint32_t* bhv = &bh[nt >> 1][(nt & 1) * 2];
                    uint32_t* blv = &bl[nt >> 1][(nt & 1) * 2];
                    MMA_BF16(acc[mt][nt], ah[mt], bhv);
                    MMA_BF16(acc[mt][nt], ah[mt], blv);
                    MMA_BF16(acc[mt][nt], al[mt], bhv);
                }
        }

        if (it + 1 < nIter) stage(cur ^ 1);
        __syncthreads();
    }

    #pragma unroll
    for (int mt = 0; mt < 2; mt++) {
        #pragma unroll
        for (int nt = 0; nt < 8; nt++) {
            int r0 = row0 + m_off + mt * 16 + lr;
            int cc = col0 + n_off + nt * 8 + lc * 2;
            float2 v0, v1;
            v0.x = acc[mt][nt][0] * alpha;
            v0.y = acc[mt][nt][1] * alpha;
            v1.x = acc[mt][nt][2] * alpha;
            v1.y = acc[mt][nt][3] * alpha;
            if (BIAS) {
                v0.x += bias[cc]; v0.y += bias[cc + 1];
                v1.x += bias[cc]; v1.y += bias[cc + 1];
            }
            *(float2*)(C + (long)r0 * ldc + cc)       = v0;
            *(float2*)(C + (long)(r0 + 8) * ldc + cc) = v1;
        }
    }
}

// ---------------------------------------------------------------------------
// Flash attention with ldmatrix fragments. smem tiles 128 x 64 words, stride 68.
// ---------------------------------------------------------------------------
#define FTW 8704
#define FTWB (FTW * 4)
#define FLASH_SMEM (6 * FTWB)   // 208896 bytes

__global__ __launch_bounds__(256, 1) void flash_kernel(
    const bf16* __restrict__ Qh, const bf16* __restrict__ Ql,
    const bf16* __restrict__ Kh, const bf16* __restrict__ Kl,
    const bf16* __restrict__ Vh, const bf16* __restrict__ Vl,
    bf16* __restrict__ Oh, bf16* __restrict__ Ol)
{
    extern __shared__ uint32_t sm[];
    __shared__ float red[4][8][4][2];

    const int h  = blockIdx.y;
    const int q0 = blockIdx.x * 128;
    const int tid = threadIdx.x;
    const int lane = tid & 31, wid = tid >> 5;
    const int m_off = (wid & 3) * 32, n_off = (wid >> 2) * 64;
    const int lr = lane >> 2, lc = lane & 3;
    const int mg = wid & 3, gg = wid >> 2;

    uint32_t* sQh = sm;
    uint32_t* sQl = sm + FTW;
    uint32_t* sPh = sm + 2 * FTW;
    uint32_t* sPl = sm + 3 * FTW;
    uint32_t* sVh = sm + 4 * FTW;
    uint32_t* sVl = sm + 5 * FTW;

    const uint32_t sbase = cvta_s(sm);
    const uint32_t aoff = ((m_off + (lane & 15)) * 68 + ((lane >> 4) & 1) * 4) * 4;
    const uint32_t boff = ((n_off + (lane & 7) + ((lane >> 4) & 1) * 8) * 68
                           + ((lane >> 3) & 1) * 4) * 4;
    const uint32_t MT_OFF = 16 * 68 * 4;

    auto load_tile = [&](uint32_t* dh, uint32_t* dl,
                         const bf16* gh, const bf16* gl,
                         int rs0, int cs0, int pitch) {
        #pragma unroll
        for (int i = 0; i < 8; i++) {
            int idx = tid + 256 * i;
            int r = idx >> 4, u = idx & 15;
            long go = (long)(rs0 + r) * pitch + cs0 + u * 8;
            *(uint4*)(dh + r * 68 + u * 4) = *(const uint4*)(gh + go);
            *(uint4*)(dl + r * 68 + u * 4) = *(const uint4*)(gl + go);
        }
    };

    load_tile(sQh, sQl, Qh, Ql, q0, h * DHEAD, DMODEL);

    float m_i[4], l_i[4], oacc[2][8][4];
    #pragma unroll
    for (int s = 0; s < 4; s++) { m_i[s] = -INFINITY; l_i[s] = 0.0f; }
    #pragma unroll
    for (int mt = 0; mt < 2; mt++)
        #pragma unroll
        for (int nt = 0; nt < 8; nt++)
            #pragma unroll
            for (int c = 0; c < 4; c++) oacc[mt][nt][c] = 0.0f;

    for (int kv = 0; kv < SEQ_TOT / 128; kv++) {
        const int kv0 = kv * 128;
        __syncthreads();
        load_tile(sPh, sPl, Kh, Kl, kv0, h * DHEAD, DMODEL);
        load_tile(sVh, sVl, Vh, Vl, h * DHEAD, kv0, SEQ_TOT);
        __syncthreads();

        // ---- S = Q @ K^T ----
        float sacc[2][8][4];
        #pragma unroll
        for (int mt = 0; mt < 2; mt++)
            #pragma unroll
            for (int nt = 0; nt < 8; nt++)
                #pragma unroll
                for (int c = 0; c < 4; c++) sacc[mt][nt][c] = 0.0f;

        #pragma unroll
        for (int ks = 0; ks < 8; ks++) {
            uint32_t ah[2][4], al[2][4], bh[4][4], bl[4][4];
            #pragma unroll
            for (int mt = 0; mt < 2; mt++) {
                LDSM_X4(ah[mt], sbase + aoff + mt * MT_OFF + ks * 32);            // sQh
                LDSM_X4(al[mt], sbase + FTWB + aoff + mt * MT_OFF + ks * 32);     // sQl
            }
            #pragma unroll
            for (int p = 0; p < 4; p++) {
                LDSM_X4(bh[p], sbase + 2 * FTWB + boff + p * MT_OFF + ks * 32);   // sPh(K)
                LDSM_X4(bl[p], sbase + 3 * FTWB + boff + p * MT_OFF + ks * 32);   // sPl(K)
            }
            #pragma unroll
            for (int mt = 0; mt < 2; mt++)
                #pragma unroll
                for (int nt = 0; nt < 8; nt++) {
                    uint32_t* bhv = &bh[nt >> 1][(nt & 1) * 2];
                    uint32_t* blv = &bl[nt >> 1][(nt & 1) * 2];
                    MMA_BF16(sacc[mt][nt], ah[mt], bhv);
                    MMA_BF16(sacc[mt][nt], ah[mt], blv);
                    MMA_BF16(sacc[mt][nt], al[mt], bhv);
                }
        }

        // ---- online softmax ----
        float mx4[4];
        #pragma unroll
        for (int s = 0; s < 4; s++) {
            int mt = s >> 1, c0 = (s & 1) * 2;
            float mx = sacc[mt][0][c0];
            #pragma unroll
            for (int nt = 0; nt < 8; nt++) {
                mx = fmaxf(mx, sacc[mt][nt][c0]);
                mx = fmaxf(mx, sacc[mt][nt][c0 + 1]);
            }
            mx = fmaxf(mx, __shfl_xor_sync(0xffffffffu, mx, 1));
            mx = fmaxf(mx, __shfl_xor_sync(0xffffffffu, mx, 2));
            mx4[s] = mx;
            if (lc == 0) red[mg][lr][s][gg] = mx;
        }
        __syncthreads();

        float a4[4], mnew[4];
        #pragma unroll
        for (int s = 0; s < 4; s++) {
            mnew[s] = fmaxf(m_i[s], fmaxf(mx4[s], red[mg][lr][s][gg ^ 1]));
            a4[s] = __expf(m_i[s] - mnew[s]);
            m_i[s] = mnew[s];
            l_i[s] *= a4[s];
        }

        float rs4[4] = {0.f, 0.f, 0.f, 0.f};
        #pragma unroll
        for (int mt = 0; mt < 2; mt++)
            #pragma unroll
            for (int nt = 0; nt < 8; nt++)
                #pragma unroll
                for (int c = 0; c < 4; c++) {
                    int s = mt * 2 + (c >> 1);
                    float e = __expf(sacc[mt][nt][c] - mnew[s]);
                    sacc[mt][nt][c] = e;
                    rs4[s] += e;
                }
        #pragma unroll
        for (int s = 0; s < 4; s++) {
            rs4[s] += __shfl_xor_sync(0xffffffffu, rs4[s], 1);
            rs4[s] += __shfl_xor_sync(0xffffffffu, rs4[s], 2);
        }
        #pragma unroll
        for (int mt = 0; mt < 2; mt++)
            #pragma unroll
            for (int nt = 0; nt < 8; nt++) {
                oacc[mt][nt][0] *= a4[mt * 2];
                oacc[mt][nt][1] *= a4[mt * 2];
                oacc[mt][nt][2] *= a4[mt * 2 + 1];
                oacc[mt][nt][3] *= a4[mt * 2 + 1];
            }
        __syncthreads();

        #pragma unroll
        for (int s = 0; s < 4; s++)
            if (lc == 0) red[mg][lr][s][gg] = rs4[s];

        // write P (bf16 hi/lo) over the K tile
        #pragma unroll
        for (int mt = 0; mt < 2; mt++)
            #pragma unroll
            for (int nt = 0; nt < 8; nt++) {
                int w = (n_off >> 1) + nt * 4 + lc;
                int o = (m_off + mt * 16 + lr) * 68 + w;
                bf16 h0, l0, h1, l1;
                bsplit(sacc[mt][nt][0], h0, l0);
                bsplit(sacc[mt][nt][1], h1, l1);
                sPh[o] = pack2(h0, h1); sPl[o] = pack2(l0, l1);
                bsplit(sacc[mt][nt][2], h0, l0);
                bsplit(sacc[mt][nt][3], h1, l1);
                sPh[o + 8 * 68] = pack2(h0, h1); sPl[o + 8 * 68] = pack2(l0, l1);
            }
        __syncthreads();

        #pragma unroll
        for (int s = 0; s < 4; s++)
            l_i[s] += rs4[s] + red[mg][lr][s][gg ^ 1];

        // ---- O += P @ V ----
        #pragma unroll
        for (int ks = 0; ks < 8; ks++) {
            uint32_t ah[2][4], al[2][4], bh[4][4], bl[4][4];
            #pragma unroll
            for (int mt = 0; mt < 2; mt++) {
                LDSM_X4(ah[mt], sbase + 2 * FTWB + aoff + mt * MT_OFF + ks * 32); // sPh
                LDSM_X4(al[mt], sbase + 3 * FTWB + aoff + mt * MT_OFF + ks * 32); // sPl
            }
            #pragma unroll
            for (int p = 0; p < 4; p++) {
                LDSM_X4(bh[p], sbase + 4 * FTWB + boff + p * MT_OFF + ks * 32);   // sVh
                LDSM_X4(bl[p], sbase + 5 * FTWB + boff + p * MT_OFF + ks * 32);   // sVl
            }
            #pragma unroll
            for (int mt = 0; mt < 2; mt++)
                #pragma unroll
                for (int nt = 0; nt < 8; nt++) {
                    uint32_t* bhv = &bh[nt >> 1][(nt & 1) * 2];
                    uint32_t* blv = &bl[nt >> 1][(nt & 1) * 2];
                    MMA_BF16(oacc[mt][nt], ah[mt], bhv);
                    MMA_BF16(oacc[mt][nt], ah[mt], blv);
                    MMA_BF16(oacc[mt][nt], al[mt], bhv);
                }
        }
    }

    // ---- epilogue ----
    #pragma unroll
    for (int mt = 0; mt < 2; mt++) {
        float i0 = 1.0f / l_i[mt * 2];
        float i1 = 1.0f / l_i[mt * 2 + 1];
        #pragma unroll
        for (int nt = 0; nt < 8; nt++) {
            int col = h * DHEAD + n_off + nt * 8 + lc * 2;
            long r0 = q0 + m_off + mt * 16 + lr;
            bf16 h0, l0, h1, l1;
            bsplit(oacc[mt][nt][0] * i0, h0, l0);
            bsplit(oacc[mt][nt][1] * i0, h1, l1);
            *(uint32_t*)(Oh + r0 * DMODEL + col) = pack2(h0, h1);
            *(uint32_t*)(Ol + r0 * DMODEL + col) = pack2(l0, l1);
            bsplit(oacc[mt][nt][2] * i1, h0, l0);
            bsplit(oacc[mt][nt][3] * i1, h1, l1);
            *(uint32_t*)(Oh + (r0 + 8) * DMODEL + col) = pack2(h0, h1);
            *(uint32_t*)(Ol + (r0 + 8) * DMODEL + col) = pack2(l0, l1);
        }
    }
}

// ---------------------------------------------------------------------------
// elementwise split
// ---------------------------------------------------------------------------
__global__ __launch_bounds__(256) void split_kernel(
    const float* __restrict__ in, bf16* __restrict__ hi, bf16* __restrict__ lo, int n4)
{
    int idx = blockIdx.x * 256 + threadIdx.x;
    if (idx >= n4) return;
    float4 v = ((const float4*)in)[idx];
    bf16 h0, l0, h1, l1, h2, l2, h3, l3;
    bsplit(v.x, h0, l0); bsplit(v.y, h1, l1);
    bsplit(v.z, h2, l2); bsplit(v.w, h3, l3);
    ((uint2*)hi)[idx] = make_uint2(pack2(h0, h1), pack2(h2, h3));
    ((uint2*)lo)[idx] = make_uint2(pack2(l0, l1), pack2(l2, l3));
}

// ---------------------------------------------------------------------------
// 32x32 tiled transpose + split (with input pitch)
// ---------------------------------------------------------------------------
__global__ __launch_bounds__(256) void transpose_split_kernel(
    const float* __restrict__ in, int in_pitch,
    bf16* __restrict__ hi, bf16* __restrict__ lo, int rows)
{
    __shared__ float t[32][33];
    int bx = blockIdx.x * 32;
    int by = blockIdx.y * 32;
    int x = bx + threadIdx.x;
    #pragma unroll
    for (int j = 0; j < 32; j += 8)
        t[threadIdx.y + j][threadIdx.x] = in[(long)(by + threadIdx.y + j) * in_pitch + x];
    __syncthreads();
    int y = by + threadIdx.x;
    #pragma unroll
    for (int j = 0; j < 32; j += 8) {
        float val = t[threadIdx.x][threadIdx.y + j];
        bf16 h, l;
        bsplit(val, h, l);
        long o = (long)(bx + threadIdx.y + j) * rows + y;
        hi[o] = h; lo[o] = l;
    }
}

// ---------------------------------------------------------------------------
// RMSNorm + RoPE + scale, split output (x has row pitch xpitch)
// ---------------------------------------------------------------------------
__global__ __launch_bounds__(128) void norm_rope_split_kernel(
    const float* __restrict__ x, int xpitch,
    bf16* __restrict__ oh, bf16* __restrict__ ol,
    const float* __restrict__ g_im,
    const float* __restrict__ g_tx,
    const float* __restrict__ freqs, float sc)
{
    int r = blockIdx.x * 4 + (threadIdx.x >> 5);
    int lane = threadIdx.x & 31;
    int s = r / NHEADS;
    int hh = r % NHEADS;

    const float* p = x + (long)s * xpitch + hh * DHEAD + lane * 4;
    float4 v = *(const float4*)p;

    float ss = v.x * v.x + v.y * v.y + v.z * v.z + v.w * v.w;
    #pragma unroll
    for (int o = 16; o; o >>= 1) ss += __shfl_xor_sync(0xffffffffu, ss, o);
    float rn = rsqrtf(ss * (1.0f / 128.0f) + 1e-5f);

    const float* g = (s < SEQ_TXT) ? g_tx : g_im;
    int d = lane * 4;
    float x0 = v.x * rn * g[d + 0];
    float x1 = v.y * rn * g[d + 1];
    float x2 = v.z * rn * g[d + 2];
    float x3 = v.w * rn * g[d + 3];

    const float* f = freqs + (long)s * 256 + (d / 2) * 4;
    float o0 = (f[0] * x0 + f[1] * x1) * sc;
    float o1 = (f[2] * x0 + f[3] * x1) * sc;
    float o2 = (f[4] * x2 + f[5] * x3) * sc;
    float o3 = (f[6] * x2 + f[7] * x3) * sc;

    bf16 h0, l0, h1, l1, h2, l2, h3, l3;
    bsplit(o0, h0, l0); bsplit(o1, h1, l1);
    bsplit(o2, h2, l2); bsplit(o3, h3, l3);
    long oi = (long)r * DHEAD + lane * 4;
    *(uint2*)(oh + oi) = make_uint2(pack2(h0, h1), pack2(h2, h3));
    *(uint2*)(ol + oi) = make_uint2(pack2(l0, l1), pack2(l2, l3));
}

// ---------------------------------------------------------------------------
extern "C" void kernel_launch(void* const* d_in, const int* in_sizes, int n_in,
                              void* d_out, int out_size)
{
    const float* hid   = (const float*)d_in[0];
    const float* enc   = (const float*)d_in[1];
    const float* freqs = (const float*)d_in[2];
    const float* W[8]  = { (const float*)d_in[3],  (const float*)d_in[4],
                           (const float*)d_in[5],  (const float*)d_in[6],
                           (const float*)d_in[7],  (const float*)d_in[8],
                           (const float*)d_in[13], (const float*)d_in[15] };
    const float* gq  = (const float*)d_in[9];
    const float* gk  = (const float*)d_in[10];
    const float* gaq = (const float*)d_in[11];
    const float* gak = (const float*)d_in[12];
    const float* bo  = (const float*)d_in[14];
    const float* bao = (const float*)d_in[16];
    float* out = (float*)d_out;

    float* qkv;
    bf16 *xh, *xl, *qh, *ql, *kh, *kl, *vth, *vtl, *ath, *atl, *wth, *wtl;
    cudaGetSymbolAddress((void**)&qkv, g_qkv);
    cudaGetSymbolAddress((void**)&xh,  g_xh);
    cudaGetSymbolAddress((void**)&xl,  g_xl);
    cudaGetSymbolAddress((void**)&qh,  g_qh);
    cudaGetSymbolAddress((void**)&ql,  g_ql);
    cudaGetSymbolAddress((void**)&kh,  g_kh);
    cudaGetSymbolAddress((void**)&kl,  g_kl);
    cudaGetSymbolAddress((void**)&vth, g_vth);
    cudaGetSymbolAddress((void**)&vtl, g_vtl);
    cudaGetSymbolAddress((void**)&ath, g_ath);
    cudaGetSymbolAddress((void**)&atl, g_atl);
    cudaGetSymbolAddress((void**)&wth, g_wth);
    cudaGetSymbolAddress((void**)&wtl, g_wtl);

    cudaFuncSetAttribute(tgemm<false>, cudaFuncAttributeMaxDynamicSharedMemorySize, SMEMB_TOTAL);
    cudaFuncSetAttribute(tgemm<true>,  cudaFuncAttributeMaxDynamicSharedMemorySize, SMEMB_TOTAL);
    cudaFuncSetAttribute(flash_kernel, cudaFuncAttributeMaxDynamicSharedMemorySize, FLASH_SMEM);

    dim3 blk(256);
    const long WSZ = (long)DMODEL * DMODEL;

    // split inputs into concatenated [enc;hid] hi/lo
    split_kernel<<<(SEQ_TXT * DMODEL / 4 + 255) / 256, 256>>>(enc, xh, xl, SEQ_TXT * DMODEL / 4);
    split_kernel<<<(SEQ_IMG * DMODEL / 4 + 255) / 256, 256>>>(
        hid, xh + (long)SEQ_TXT * DMODEL, xl + (long)SEQ_TXT * DMODEL, SEQ_IMG * DMODEL / 4);

    // transpose + split weights
    for (int i = 0; i < 8; i++)
        transpose_split_kernel<<<dim3(96, 96), dim3(32, 8)>>>(
            W[i], DMODEL, wth + i * WSZ, wtl + i * WSZ, DMODEL);

    // Fused QKV projections (N=9216). W rows: [Wq|Wk|Wv] and [Waq|Wak|Wav]
    tgemm<false><<<dim3(QKVP / 128, 2, 1), blk, SMEMB_TOTAL>>>(
        xh, xl, DMODEL,
        wth + 3 * WSZ, wtl + 3 * WSZ, DMODEL,
        qkv, QKVP, DMODEL, nullptr, 1.0f);
    tgemm<false><<<dim3(QKVP / 128, 16, 1), blk, SMEMB_TOTAL>>>(
        xh + (long)SEQ_TXT * DMODEL, xl + (long)SEQ_TXT * DMODEL, DMODEL,
        wth, wtl, DMODEL,
        qkv + (long)SEQ_TXT * QKVP, QKVP, DMODEL, nullptr, 1.0f);

    // RMSNorm + RoPE + split (scale folded into q)
    const float scale = 0.088388347648318447f;
    norm_rope_split_kernel<<<SEQ_TOT * NHEADS / 4, 128>>>(
        qkv, QKVP, qh, ql, gq, gaq, freqs, scale);
    norm_rope_split_kernel<<<SEQ_TOT * NHEADS / 4, 128>>>(
        qkv + DMODEL, QKVP, kh, kl, gk, gak, freqs, 1.0f);

    // transpose + split V (cols 6144.. of qkv)
    transpose_split_kernel<<<dim3(96, 72), dim3(32, 8)>>>(
        qkv + 2 * DMODEL, QKVP, vth, vtl, SEQ_TOT);

    // fused attention -> ath/atl
    flash_kernel<<<dim3(SEQ_TOT / 128, NHEADS), blk, FLASH_SMEM>>>(
        qh, ql, kh, kl, vth, vtl, ath, atl);

    // Output projections (img first, then txt)
    tgemm<true><<<dim3(24, 16, 1), blk, SMEMB_TOTAL>>>(
        ath + (long)SEQ_TXT * DMODEL, atl + (long)SEQ_TXT * DMODEL, DMODEL,
        wth + 6 * WSZ, wtl + 6 * WSZ, DMODEL,
        out, DMODEL, DMODEL, bo, 1.0f);
    tgemm<true><<<dim3(24, 2, 1), blk, SMEMB_TOTAL>>>(
        ath, atl, DMODEL,
        wth + 7 * WSZ, wtl + 7 * WSZ, DMODEL,
        out + (long)SEQ_IMG * DMODEL, DMODEL, DMODEL, bao, 1.0f);
}

// round 9
// speedup vs baseline: 4.3925x; 1.0969x over previous
#include <cuda_runtime.h>
#include <cuda_bf16.h>
#include <math.h>
#include <stdint.h>

#define SEQ_TXT 256
#define SEQ_IMG 2048
#define SEQ_TOT 2304
#define DMODEL  3072
#define NHEADS  24
#define DHEAD   128
#define QKVP    (3 * DMODEL)

typedef __nv_bfloat16 bf16;

// fp32 scratch: concatenated [q|k|v] per row
__device__ float g_qkv[SEQ_TOT * (long)QKVP];

// bf16 hi/lo pre-split operands
__device__ bf16 g_xh[SEQ_TOT * DMODEL],  g_xl[SEQ_TOT * DMODEL];
__device__ bf16 g_qh[SEQ_TOT * DMODEL],  g_ql[SEQ_TOT * DMODEL];
__device__ bf16 g_kh[SEQ_TOT * DMODEL],  g_kl[SEQ_TOT * DMODEL];
__device__ bf16 g_vth[DMODEL * SEQ_TOT], g_vtl[DMODEL * SEQ_TOT];
__device__ bf16 g_ath[SEQ_TOT * DMODEL], g_atl[SEQ_TOT * DMODEL];
__device__ bf16 g_wth[8][DMODEL * (long)DMODEL];
__device__ bf16 g_wtl[8][DMODEL * (long)DMODEL];

__device__ __forceinline__ void bsplit(float x, bf16& h, bf16& l) {
    h = __float2bfloat16_rn(x);
    l = __float2bfloat16_rn(x - __bfloat162float(h));
}
__device__ __forceinline__ uint32_t pack2(bf16 a, bf16 b) {
    __nv_bfloat162 t = __halves2bfloat162(a, b);
    return *(uint32_t*)&t;
}
__device__ __forceinline__ uint32_t cvta_s(const void* p) {
    return (uint32_t)__cvta_generic_to_shared(p);
}

#define MMA_BF16(CV, AV, BV) \
    asm volatile( \
        "mma.sync.aligned.m16n8k16.row.col.f32.bf16.bf16.f32 " \
        "{%0,%1,%2,%3}, {%4,%5,%6,%7}, {%8,%9}, {%0,%1,%2,%3};" \
        : "+f"((CV)[0]), "+f"((CV)[1]), "+f"((CV)[2]), "+f"((CV)[3]) \
        : "r"((AV)[0]), "r"((AV)[1]), "r"((AV)[2]), "r"((AV)[3]), \
          "r"((BV)[0]), "r"((BV)[1]))

#define LDSM_X4(R, ADDR) \
    asm volatile("ldmatrix.sync.aligned.m8n8.x4.shared.b16 {%0,%1,%2,%3}, [%4];" \
        : "=r"((R)[0]), "=r"((R)[1]), "=r"((R)[2]), "=r"((R)[3]) : "r"(ADDR))

#define CP_ASYNC16(dst, src) \
    asm volatile("cp.async.cg.shared.global [%0], [%1], 16;" \
        :: "r"(dst), "l"(src) : "memory")
#define CP_COMMIT() asm volatile("cp.async.commit_group;" ::: "memory")
#define CP_WAIT(N)  asm volatile("cp.async.wait_group %0;" :: "n"(N) : "memory")

// ---------------------------------------------------------------------------
// bf16x3 tensor-core GEMM, cp.async 2-stage pipeline, 2 CTAs/SM.
// C = alpha * A @ B^T (+bias). Blocks with blockIdx.y < ysplit use B2/bias2.
// cremap=1: txt A-rows (y<ysplit) map to C rows SEQ_IMG+, img rows shift -256.
// smem per stage: [Ahi][Alo][Bhi][Blo], row stride 20 words.
// ---------------------------------------------------------------------------
#define WSTRIDE 20
#define TILE_WORDS (128 * WSTRIDE)
#define TWB (TILE_WORDS * 4)
#define SMEMB_TOTAL (8 * TWB)   // 81920 bytes

template<bool BIAS>
__global__ __launch_bounds__(256, 2) void tgemm(
    const bf16* __restrict__ Ahi, const bf16* __restrict__ Alo, int lda,
    const bf16* __restrict__ Bhi, const bf16* __restrict__ Blo,
    const bf16* __restrict__ B2hi, const bf16* __restrict__ B2lo,
    int ldb, int ysplit,
    float* __restrict__ C, int ldc, int cremap,
    int K, const float* __restrict__ bias, const float* __restrict__ bias2,
    float alpha)
{
    extern __shared__ uint32_t sm[];

    const bool txt = (int)blockIdx.y < ysplit;
    const bf16* Bh = txt ? B2hi : Bhi;
    const bf16* Bl = txt ? B2lo : Blo;
    const float* bptr = txt ? bias2 : bias;

    const int row0 = blockIdx.y * 128;
    const int col0 = blockIdx.x * 128;
    int crow0 = row0;
    if (cremap) crow0 = txt ? (SEQ_IMG + row0) : (row0 - SEQ_TXT);

    const int tid = threadIdx.x;
    const int lane = tid & 31, wid = tid >> 5;
    const int m_off = (wid & 3) * 32, n_off = (wid >> 2) * 64;
    const int lr = lane >> 2, lc = lane & 3;

    const uint32_t sbase = cvta_s(sm);
    const uint32_t aoff = ((m_off + (lane & 15)) * WSTRIDE + ((lane >> 4) & 1) * 4) * 4;
    const uint32_t boff = ((n_off + (lane & 7) + ((lane >> 4) & 1) * 8) * WSTRIDE
                           + ((lane >> 3) & 1) * 4) * 4;
    const uint32_t MT_OFF = 16 * WSTRIDE * 4;

    const int pr = tid >> 2, pw = (tid & 3) * 4;

    auto issue = [&](int k0, int buf) {
        uint32_t sb = sbase + buf * 4 * TWB;
        #pragma unroll
        for (int p = 0; p < 2; p++) {
            int row = pr + p * 64;
            uint32_t so = (uint32_t)(row * WSTRIDE + pw) * 4;
            long ro = (long)(row0 + row) * lda + k0 + pw * 2;
            long co = (long)(col0 + row) * ldb + k0 + pw * 2;
            CP_ASYNC16(sb + so,             Ahi + ro);
            CP_ASYNC16(sb + TWB + so,       Alo + ro);
            CP_ASYNC16(sb + 2 * TWB + so,   Bh + co);
            CP_ASYNC16(sb + 3 * TWB + so,   Bl + co);
        }
        CP_COMMIT();
    };

    issue(0, 0);

    float acc[2][8][4];
    #pragma unroll
    for (int mt = 0; mt < 2; mt++)
        #pragma unroll
        for (int nt = 0; nt < 8; nt++)
            #pragma unroll
            for (int i = 0; i < 4; i++) acc[mt][nt][i] = 0.0f;

    CP_WAIT(0);
    __syncthreads();

    const int nIter = K >> 5;
    for (int it = 0; it < nIter; ++it) {
        const int cur = it & 1;
        if (it + 1 < nIter) issue((it + 1) * 32, cur ^ 1);
        const uint32_t stg = sbase + cur * 4 * TWB;

        #pragma unroll
        for (int ks = 0; ks < 2; ks++) {
            uint32_t ah[2][4], al[2][4], bh[4][4], bl[4][4];
            #pragma unroll
            for (int mt = 0; mt < 2; mt++) {
                LDSM_X4(ah[mt], stg + aoff + mt * MT_OFF + ks * 32);
                LDSM_X4(al[mt], stg + TWB + aoff + mt * MT_OFF + ks * 32);
            }
            #pragma unroll
            for (int p = 0; p < 4; p++) {
                LDSM_X4(bh[p], stg + 2 * TWB + boff + p * MT_OFF + ks * 32);
                LDSM_X4(bl[p], stg + 3 * TWB + boff + p * MT_OFF + ks * 32);
            }
            #pragma unroll
            for (int mt = 0; mt < 2; mt++)
                #pragma unroll
                for (int nt = 0; nt < 8; nt++) {
                    uint32_t* bhv = &bh[nt >> 1][(nt & 1) * 2];
                    uint32_t* blv = &bl[nt >> 1][(nt & 1) * 2];
                    MMA_BF16(acc[mt][nt], ah[mt], bhv);
                    MMA_BF16(acc[mt][nt], ah[mt], blv);
                    MMA_BF16(acc[mt][nt], al[mt], bhv);
                }
        }

        if (it + 1 < nIter) CP_WAIT(0);
        __syncthreads();
    }

    #pragma unroll
    for (int mt = 0; mt < 2; mt++) {
        #pragma unroll
        for (int nt = 0; nt < 8; nt++) {
            int r0 = crow0 + m_off + mt * 16 + lr;
            int cc = col0 + n_off + nt * 8 + lc * 2;
            float2 v0, v1;
            v0.x = acc[mt][nt][0] * alpha;
            v0.y = acc[mt][nt][1] * alpha;
            v1.x = acc[mt][nt][2] * alpha;
            v1.y = acc[mt][nt][3] * alpha;
            if (BIAS) {
                v0.x += bptr[cc]; v0.y += bptr[cc + 1];
                v1.x += bptr[cc]; v1.y += bptr[cc + 1];
            }
            *(float2*)(C + (long)r0 * ldc + cc)       = v0;
            *(float2*)(C + (long)(r0 + 8) * ldc + cc) = v1;
        }
    }
}

// ---------------------------------------------------------------------------
// Flash attention: cp.async tile loads, V prefetch hidden behind S-phase.
// ---------------------------------------------------------------------------
#define FTW 8704
#define FTWB (FTW * 4)
#define FLASH_SMEM (6 * FTWB)   // 208896 bytes

__global__ __launch_bounds__(256, 1) void flash_kernel(
    const bf16* __restrict__ Qh, const bf16* __restrict__ Ql,
    const bf16* __restrict__ Kh, const bf16* __restrict__ Kl,
    const bf16* __restrict__ Vh, const bf16* __restrict__ Vl,
    bf16* __restrict__ Oh, bf16* __restrict__ Ol)
{
    extern __shared__ uint32_t sm[];
    __shared__ float red[4][8][4][2];

    const int h  = blockIdx.y;
    const int q0 = blockIdx.x * 128;
    const int tid = threadIdx.x;
    const int lane = tid & 31, wid = tid >> 5;
    const int m_off = (wid & 3) * 32, n_off = (wid >> 2) * 64;
    const int lr = lane >> 2, lc = lane & 3;
    const int mg = wid & 3, gg = wid >> 2;

    uint32_t* sPh = sm + 2 * FTW;
    uint32_t* sPl = sm + 3 * FTW;

    const uint32_t sbase = cvta_s(sm);
    const uint32_t aoff = ((m_off + (lane & 15)) * 68 + ((lane >> 4) & 1) * 4) * 4;
    const uint32_t boff = ((n_off + (lane & 7) + ((lane >> 4) & 1) * 8) * 68
                           + ((lane >> 3) & 1) * 4) * 4;
    const uint32_t MT_OFF = 16 * 68 * 4;

    auto issue_tile = [&](uint32_t dhb, uint32_t dlb,
                          const bf16* gh, const bf16* gl,
                          int rs0, int cs0, int pitch) {
        #pragma unroll
        for (int i = 0; i < 8; i++) {
            int idx = tid + 256 * i;
            int r = idx >> 4, u = idx & 15;
            long go = (long)(rs0 + r) * pitch + cs0 + u * 8;
            uint32_t so = (uint32_t)(r * 68 + u * 4) * 4;
            CP_ASYNC16(dhb + so, gh + go);
            CP_ASYNC16(dlb + so, gl + go);
        }
        CP_COMMIT();
    };

    // Q (persistent) — group committed, covered by first wait
    issue_tile(sbase, sbase + FTWB, Qh, Ql, q0, h * DHEAD, DMODEL);

    float m_i[4], l_i[4], oacc[2][8][4];
    #pragma unroll
    for (int s = 0; s < 4; s++) { m_i[s] = -INFINITY; l_i[s] = 0.0f; }
    #pragma unroll
    for (int mt = 0; mt < 2; mt++)
        #pragma unroll
        for (int nt = 0; nt < 8; nt++)
            #pragma unroll
            for (int c = 0; c < 4; c++) oacc[mt][nt][c] = 0.0f;

    for (int kv = 0; kv < SEQ_TOT / 128; kv++) {
        const int kv0 = kv * 128;
        __syncthreads();   // prior PV reads of sP/sV complete
        issue_tile(sbase + 2 * FTWB, sbase + 3 * FTWB, Kh, Kl, kv0, h * DHEAD, DMODEL);
        issue_tile(sbase + 4 * FTWB, sbase + 5 * FTWB, Vh, Vl, h * DHEAD, kv0, SEQ_TOT);
        CP_WAIT(1);        // Q (first iter) + K ready; V may still be in flight
        __syncthreads();

        // ---- S = Q @ K^T ----
        float sacc[2][8][4];
        #pragma unroll
        for (int mt = 0; mt < 2; mt++)
            #pragma unroll
            for (int nt = 0; nt < 8; nt++)
                #pragma unroll
                for (int c = 0; c < 4; c++) sacc[mt][nt][c] = 0.0f;

        #pragma unroll
        for (int ks = 0; ks < 8; ks++) {
            uint32_t ah[2][4], al[2][4], bh[4][4], bl[4][4];
            #pragma unroll
            for (int mt = 0; mt < 2; mt++) {
                LDSM_X4(ah[mt], sbase + aoff + mt * MT_OFF + ks * 32);
                LDSM_X4(al[mt], sbase + FTWB + aoff + mt * MT_OFF + ks * 32);
            }
            #pragma unroll
            for (int p = 0; p < 4; p++) {
                LDSM_X4(bh[p], sbase + 2 * FTWB + boff + p * MT_OFF + ks * 32);
                LDSM_X4(bl[p], sbase + 3 * FTWB + boff + p * MT_OFF + ks * 32);
            }
            #pragma unroll
            for (int mt = 0; mt < 2; mt++)
                #pragma unroll
                for (int nt = 0; nt < 8; nt++) {
                    uint32_t* bhv = &bh[nt >> 1][(nt & 1) * 2];
                    uint32_t* blv = &bl[nt >> 1][(nt & 1) * 2];
                    MMA_BF16(sacc[mt][nt], ah[mt], bhv);
                    MMA_BF16(sacc[mt][nt], ah[mt], blv);
                    MMA_BF16(sacc[mt][nt], al[mt], bhv);
                }
        }

        // ---- online softmax ----
        float mx4[4];
        #pragma unroll
        for (int s = 0; s < 4; s++) {
            int mt = s >> 1, c0 = (s & 1) * 2;
            float mx = sacc[mt][0][c0];
            #pragma unroll
            for (int nt = 0; nt < 8; nt++) {
                mx = fmaxf(mx, sacc[mt][nt][c0]);
                mx = fmaxf(mx, sacc[mt][nt][c0 + 1]);
            }
            mx = fmaxf(mx, __shfl_xor_sync(0xffffffffu, mx, 1));
            mx = fmaxf(mx, __shfl_xor_sync(0xffffffffu, mx, 2));
            mx4[s] = mx;
            if (lc == 0) red[mg][lr][s][gg] = mx;
        }
        __syncthreads();

        float a4[4], mnew[4];
        #pragma unroll
        for (int s = 0; s < 4; s++) {
            mnew[s] = fmaxf(m_i[s], fmaxf(mx4[s], red[mg][lr][s][gg ^ 1]));
            a4[s] = __expf(m_i[s] - mnew[s]);
            m_i[s] = mnew[s];
            l_i[s] *= a4[s];
        }

        float rs4[4] = {0.f, 0.f, 0.f, 0.f};
        #pragma unroll
        for (int mt = 0; mt < 2; mt++)
            #pragma unroll
            for (int nt = 0; nt < 8; nt++)
                #pragma unroll
                for (int c = 0; c < 4; c++) {
                    int s = mt * 2 + (c >> 1);
                    float e = __expf(sacc[mt][nt][c] - mnew[s]);
                    sacc[mt][nt][c] = e;
                    rs4[s] += e;
                }
        #pragma unroll
        for (int s = 0; s < 4; s++) {
            rs4[s] += __shfl_xor_sync(0xffffffffu, rs4[s], 1);
            rs4[s] += __shfl_xor_sync(0xffffffffu, rs4[s], 2);
        }
        #pragma unroll
        for (int mt = 0; mt < 2; mt++)
            #pragma unroll
            for (int nt = 0; nt < 8; nt++) {
                oacc[mt][nt][0] *= a4[mt * 2];
                oacc[mt][nt][1] *= a4[mt * 2];
                oacc[mt][nt][2] *= a4[mt * 2 + 1];
                oacc[mt][nt][3] *= a4[mt * 2 + 1];
            }
        __syncthreads();   // S-mma reads of sP done in all warps

        #pragma unroll
        for (int s = 0; s < 4; s++)
            if (lc == 0) red[mg][lr][s][gg] = rs4[s];

        // write P (bf16 hi/lo) over the K tile
        #pragma unroll
        for (int mt = 0; mt < 2; mt++)
            #pragma unroll
            for (int nt = 0; nt < 8; nt++) {
                int w = (n_off >> 1) + nt * 4 + lc;
                int o = (m_off + mt * 16 + lr) * 68 + w;
                bf16 h0, l0, h1, l1;
                bsplit(sacc[mt][nt][0], h0, l0);
                bsplit(sacc[mt][nt][1], h1, l1);
                sPh[o] = pack2(h0, h1); sPl[o] = pack2(l0, l1);
                bsplit(sacc[mt][nt][2], h0, l0);
                bsplit(sacc[mt][nt][3], h1, l1);
                sPh[o + 8 * 68] = pack2(h0, h1); sPl[o + 8 * 68] = pack2(l0, l1);
            }
        CP_WAIT(0);        // V tile landed (hidden behind S + softmax)
        __syncthreads();

        #pragma unroll
        for (int s = 0; s < 4; s++)
            l_i[s] += rs4[s] + red[mg][lr][s][gg ^ 1];

        // ---- O += P @ V ----
        #pragma unroll
        for (int ks = 0; ks < 8; ks++) {
            uint32_t ah[2][4], al[2][4], bh[4][4], bl[4][4];
            #pragma unroll
            for (int mt = 0; mt < 2; mt++) {
                LDSM_X4(ah[mt], sbase + 2 * FTWB + aoff + mt * MT_OFF + ks * 32);
                LDSM_X4(al[mt], sbase + 3 * FTWB + aoff + mt * MT_OFF + ks * 32);
            }
            #pragma unroll
            for (int p = 0; p < 4; p++) {
                LDSM_X4(bh[p], sbase + 4 * FTWB + boff + p * MT_OFF + ks * 32);
                LDSM_X4(bl[p], sbase + 5 * FTWB + boff + p * MT_OFF + ks * 32);
            }
            #pragma unroll
            for (int mt = 0; mt < 2; mt++)
                #pragma unroll
                for (int nt = 0; nt < 8; nt++) {
                    uint32_t* bhv = &bh[nt >> 1][(nt & 1) * 2];
                    uint32_t* blv = &bl[nt >> 1][(nt & 1) * 2];
                    MMA_BF16(oacc[mt][nt], ah[mt], bhv);
                    MMA_BF16(oacc[mt][nt], ah[mt], blv);
                    MMA_BF16(oacc[mt][nt], al[mt], bhv);
                }
        }
    }

    // ---- epilogue ----
    #pragma unroll
    for (int mt = 0; mt < 2; mt++) {
        float i0 = 1.0f / l_i[mt * 2];
        float i1 = 1.0f / l_i[mt * 2 + 1];
        #pragma unroll
        for (int nt = 0; nt < 8; nt++) {
            int col = h * DHEAD + n_off + nt * 8 + lc * 2;
            long r0 = q0 + m_off + mt * 16 + lr;
            bf16 h0, l0, h1, l1;
            bsplit(oacc[mt][nt][0] * i0, h0, l0);
            bsplit(oacc[mt][nt][1] * i0, h1, l1);
            *(uint32_t*)(Oh + r0 * DMODEL + col) = pack2(h0, h1);
            *(uint32_t*)(Ol + r0 * DMODEL + col) = pack2(l0, l1);
            bsplit(oacc[mt][nt][2] * i1, h0, l0);
            bsplit(oacc[mt][nt][3] * i1, h1, l1);
            *(uint32_t*)(Oh + (r0 + 8) * DMODEL + col) = pack2(h0, h1);
            *(uint32_t*)(Ol + (r0 + 8) * DMODEL + col) = pack2(l0, l1);
        }
    }
}

// ---------------------------------------------------------------------------
// Prep: z<8 -> transpose+split weight z; z==8 -> split [enc;hid] inputs.
// ---------------------------------------------------------------------------
__global__ __launch_bounds__(256) void prep_kernel(
    const float* __restrict__ hid, const float* __restrict__ enc,
    const float* W0, const float* W1, const float* W2, const float* W3,
    const float* W4, const float* W5, const float* W6, const float* W7,
    bf16* __restrict__ wth, bf16* __restrict__ wtl,
    bf16* __restrict__ xh, bf16* __restrict__ xl)
{
    __shared__ float t[32][33];
    const int z = blockIdx.z;

    if (z == 8) {
        int idx = (blockIdx.y * 96 + blockIdx.x) * 256 + threadIdx.y * 32 + threadIdx.x;
        const int TOT4 = SEQ_TOT * DMODEL / 4;
        const int TXT4 = SEQ_TXT * DMODEL / 4;
        if (idx < TOT4) {
            float4 v = (idx < TXT4) ? ((const float4*)enc)[idx]
                                    : ((const float4*)hid)[idx - TXT4];
            bf16 h0, l0, h1, l1, h2, l2, h3, l3;
            bsplit(v.x, h0, l0); bsplit(v.y, h1, l1);
            bsplit(v.z, h2, l2); bsplit(v.w, h3, l3);
            ((uint2*)xh)[idx] = make_uint2(pack2(h0, h1), pack2(h2, h3));
            ((uint2*)xl)[idx] = make_uint2(pack2(l0, l1), pack2(l2, l3));
        }
        return;
    }

    const float* Ws = W0;
    switch (z) {
        case 1: Ws = W1; break; case 2: Ws = W2; break; case 3: Ws = W3; break;
        case 4: Ws = W4; break; case 5: Ws = W5; break; case 6: Ws = W6; break;
        case 7: Ws = W7; break; default: break;
    }
    bf16* hi = wth + (long)z * DMODEL * DMODEL;
    bf16* lo = wtl + (long)z * DMODEL * DMODEL;

    int bx = blockIdx.x * 32;
    int by = blockIdx.y * 32;
    int x = bx + threadIdx.x;
    #pragma unroll
    for (int j = 0; j < 32; j += 8)
        t[threadIdx.y + j][threadIdx.x] = Ws[(long)(by + threadIdx.y + j) * DMODEL + x];
    __syncthreads();
    int y = by + threadIdx.x;
    #pragma unroll
    for (int j = 0; j < 32; j += 8) {
        float val = t[threadIdx.x][threadIdx.y + j];
        bf16 h, l;
        bsplit(val, h, l);
        long o = (long)(bx + threadIdx.y + j) * DMODEL + y;
        hi[o] = h; lo[o] = l;
    }
}

// ---------------------------------------------------------------------------
// 32x32 transpose + split (for V, input pitch QKVP)
// ---------------------------------------------------------------------------
__global__ __launch_bounds__(256) void transpose_split_kernel(
    const float* __restrict__ in, int in_pitch,
    bf16* __restrict__ hi, bf16* __restrict__ lo, int rows)
{
    __shared__ float t[32][33];
    int bx = blockIdx.x * 32;
    int by = blockIdx.y * 32;
    int x = bx + threadIdx.x;
    #pragma unroll
    for (int j = 0; j < 32; j += 8)
        t[threadIdx.y + j][threadIdx.x] = in[(long)(by + threadIdx.y + j) * in_pitch + x];
    __syncthreads();
    int y = by + threadIdx.x;
    #pragma unroll
    for (int j = 0; j < 32; j += 8) {
        float val = t[threadIdx.x][threadIdx.y + j];
        bf16 h, l;
        bsplit(val, h, l);
        long o = (long)(bx + threadIdx.y + j) * rows + y;
        hi[o] = h; lo[o] = l;
    }
}

// ---------------------------------------------------------------------------
// Fused RMSNorm + RoPE + scale for q (y=0) and k (y=1); split output.
// ---------------------------------------------------------------------------
__global__ __launch_bounds__(128) void norm_rope_split_kernel(
    const float* __restrict__ qkv,
    bf16* __restrict__ qh, bf16* __restrict__ ql,
    bf16* __restrict__ kh, bf16* __restrict__ kl,
    const float* __restrict__ gq, const float* __restrict__ gaq,
    const float* __restrict__ gk, const float* __restrict__ gak,
    const float* __restrict__ freqs, float qscale)
{
    const bool isq = (blockIdx.y == 0);
    const float* x = qkv + (isq ? 0 : DMODEL);
    bf16* oh = isq ? qh : kh;
    bf16* ol = isq ? ql : kl;
    const float* g_im = isq ? gq : gk;
    const float* g_tx = isq ? gaq : gak;
    const float sc = isq ? qscale : 1.0f;

    int r = blockIdx.x * 4 + (threadIdx.x >> 5);
    int lane = threadIdx.x & 31;
    int s = r / NHEADS;
    int hh = r % NHEADS;

    const float* p = x + (long)s * QKVP + hh * DHEAD + lane * 4;
    float4 v = *(const float4*)p;

    float ss = v.x * v.x + v.y * v.y + v.z * v.z + v.w * v.w;
    #pragma unroll
    for (int o = 16; o; o >>= 1) ss += __shfl_xor_sync(0xffffffffu, ss, o);
    float rn = rsqrtf(ss * (1.0f / 128.0f) + 1e-5f);

    const float* g = (s < SEQ_TXT) ? g_tx : g_im;
    int d = lane * 4;
    float x0 = v.x * rn * g[d + 0];
    float x1 = v.y * rn * g[d + 1];
    float x2 = v.z * rn * g[d + 2];
    float x3 = v.w * rn * g[d + 3];

    const float* f = freqs + (long)s * 256 + (d / 2) * 4;
    float o0 = (f[0] * x0 + f[1] * x1) * sc;
    float o1 = (f[2] * x0 + f[3] * x1) * sc;
    float o2 = (f[4] * x2 + f[5] * x3) * sc;
    float o3 = (f[6] * x2 + f[7] * x3) * sc;

    bf16 h0, l0, h1, l1, h2, l2, h3, l3;
    bsplit(o0, h0, l0); bsplit(o1, h1, l1);
    bsplit(o2, h2, l2); bsplit(o3, h3, l3);
    long oi = (long)r * DHEAD + lane * 4;
    *(uint2*)(oh + oi) = make_uint2(pack2(h0, h1), pack2(h2, h3));
    *(uint2*)(ol + oi) = make_uint2(pack2(l0, l1), pack2(l2, l3));
}

// ---------------------------------------------------------------------------
extern "C" void kernel_launch(void* const* d_in, const int* in_sizes, int n_in,
                              void* d_out, int out_size)
{
    const float* hid   = (const float*)d_in[0];
    const float* enc   = (const float*)d_in[1];
    const float* freqs = (const float*)d_in[2];
    const float* gq  = (const float*)d_in[9];
    const float* gk  = (const float*)d_in[10];
    const float* gaq = (const float*)d_in[11];
    const float* gak = (const float*)d_in[12];
    const float* bo  = (const float*)d_in[14];
    const float* bao = (const float*)d_in[16];
    float* out = (float*)d_out;

    float* qkv;
    bf16 *xh, *xl, *qh, *ql, *kh, *kl, *vth, *vtl, *ath, *atl, *wth, *wtl;
    cudaGetSymbolAddress((void**)&qkv, g_qkv);
    cudaGetSymbolAddress((void**)&xh,  g_xh);
    cudaGetSymbolAddress((void**)&xl,  g_xl);
    cudaGetSymbolAddress((void**)&qh,  g_qh);
    cudaGetSymbolAddress((void**)&ql,  g_ql);
    cudaGetSymbolAddress((void**)&kh,  g_kh);
    cudaGetSymbolAddress((void**)&kl,  g_kl);
    cudaGetSymbolAddress((void**)&vth, g_vth);
    cudaGetSymbolAddress((void**)&vtl, g_vtl);
    cudaGetSymbolAddress((void**)&ath, g_ath);
    cudaGetSymbolAddress((void**)&atl, g_atl);
    cudaGetSymbolAddress((void**)&wth, g_wth);
    cudaGetSymbolAddress((void**)&wtl, g_wtl);

    cudaFuncSetAttribute(tgemm<false>, cudaFuncAttributeMaxDynamicSharedMemorySize, SMEMB_TOTAL);
    cudaFuncSetAttribute(tgemm<true>,  cudaFuncAttributeMaxDynamicSharedMemorySize, SMEMB_TOTAL);
    cudaFuncSetAttribute(flash_kernel, cudaFuncAttributeMaxDynamicSharedMemorySize, FLASH_SMEM);

    const long WSZ = (long)DMODEL * DMODEL;

    // 1) prep: weights transpose+split (z 0..7) + input split (z 8)
    prep_kernel<<<dim3(96, 96, 9), dim3(32, 8)>>>(
        hid, enc,
        (const float*)d_in[3],  (const float*)d_in[4],  (const float*)d_in[5],
        (const float*)d_in[6],  (const float*)d_in[7],  (const float*)d_in[8],
        (const float*)d_in[13], (const float*)d_in[15],
        wth, wtl, xh, xl);

    // 2) fused QKV: y<2 -> txt weights (Waq|Wak|Wav), else img (Wq|Wk|Wv)
    tgemm<false><<<dim3(QKVP / 128, SEQ_TOT / 128), 256, SMEMB_TOTAL>>>(
        xh, xl, DMODEL,
        wth, wtl, wth + 3 * WSZ, wtl + 3 * WSZ, DMODEL, 2,
        qkv, QKVP, 0, DMODEL, nullptr, nullptr, 1.0f);

    // 3) fused RMSNorm+RoPE+split for q (scaled) and k
    const float scale = 0.088388347648318447f;
    norm_rope_split_kernel<<<dim3(SEQ_TOT * NHEADS / 4, 2), 128>>>(
        qkv, qh, ql, kh, kl, gq, gaq, gk, gak, freqs, scale);

    // 4) transpose+split V
    transpose_split_kernel<<<dim3(96, 72), dim3(32, 8)>>>(
        qkv + 2 * DMODEL, QKVP, vth, vtl, SEQ_TOT);

    // 5) flash attention -> ath/atl
    flash_kernel<<<dim3(SEQ_TOT / 128, NHEADS), 256, FLASH_SMEM>>>(
        qh, ql, kh, kl, vth, vtl, ath, atl);

    // 6) fused output projection: y<2 -> txt rows (Wao/bao -> out rows 2048+),
    //    else img rows (Wo/bo -> out rows 0..2047)
    tgemm<true><<<dim3(24, SEQ_TOT / 128), 256, SMEMB_TOTAL>>>(
        ath, atl, DMODEL,
        wth + 6 * WSZ, wtl + 6 * WSZ, wth + 7 * WSZ, wtl + 7 * WSZ, DMODEL, 2,
        out, DMODEL, 1, DMODEL, bo, bao, 1.0f);
}